// round 1
// baseline (speedup 1.0000x reference)
#include <cuda_runtime.h>

#define NEG 1e30f

namespace {
constexpr int Bsz = 8;
constexpr int Npat = 196;      // 14*14 patches
constexpr int PD  = 256;       // 16*16 patch dim
constexpr int D   = 128;
constexpr int DFF = 256;
constexpr int Cls = 1000;
constexpr int Mrows = Bsz * Npat;  // 1568
}

// ---------------- scratch (device globals; no allocation allowed) ----------
__device__ float g_patches[Mrows * PD];
__device__ float g_h   [Mrows * D];
__device__ float g_xn  [Mrows * D];
__device__ float g_q   [Mrows * D];
__device__ float g_k   [Mrows * D];
__device__ float g_v   [Mrows * D];
__device__ float g_sc  [Bsz * Npat * Npat];
__device__ float g_attn[Mrows * D];
__device__ float g_ffh [Mrows * DFF];
__device__ float g_ffo [Mrows * D];
__device__ float g_pool[Bsz * D];

// ---------------- patchify: (8,224,224) -> (1568,256) ----------------------
__global__ void patchify_kernel(const float* __restrict__ x, float* __restrict__ out) {
    int m = blockIdx.x;          // 0..1567
    int kk = threadIdx.x;        // 0..255
    int b = m / Npat, n = m % Npat;
    int gy = n / 14, gx = n % 14;
    int py = kk / 16, px = kk % 16;
    out[m * PD + kk] = x[b * 224 * 224 + (gy * 16 + py) * 224 + gx * 16 + px];
}

// ---------------- tropical GEMM: C[m,n] = max_k (A[m,k] + B[n,k] or B[k,n]) -
// BMODE 0: B is [N][K] row-major (TN).  BMODE 1: B is [K][N] row-major (NN).
// epi: 0 none, 1 add pos[(m%196)*Nc + n], 2 max with epi_ptr[0] (tau)
template<int BMODE>
__global__ __launch_bounds__(256)
void trop_gemm(const float* __restrict__ A, const float* __restrict__ Bm,
               float* __restrict__ Cm,
               int Mr, int Nc, int K,
               long aStride, long bStride, long cStride,
               int epi, const float* __restrict__ epi_ptr)
{
    A  += (long)blockIdx.z * aStride;
    Bm += (long)blockIdx.z * bStride;
    Cm += (long)blockIdx.z * cStride;

    __shared__ float As[16][64];
    __shared__ float Bs[16][64];

    const int bm = blockIdx.x * 64;
    const int bn = blockIdx.y * 64;
    const int tid = threadIdx.x;
    const int tx = tid & 15, ty = tid >> 4;

    float acc[4][4];
#pragma unroll
    for (int i = 0; i < 4; i++)
#pragma unroll
        for (int j = 0; j < 4; j++) acc[i][j] = -NEG;

    const int a_row = tid >> 2, a_k = (tid & 3) << 2;        // A: 64 rows x 16 k
    const int bk_nn = tid >> 4, bn_nn = (tid & 15) << 2;     // B NN: 16 k x 64 n

    for (int k0 = 0; k0 < K; k0 += 16) {
        // ---- stage A tile (transposed into smem) ----
        {
            int gm = bm + a_row, gk = k0 + a_k;
            float4 v = make_float4(-NEG, -NEG, -NEG, -NEG);
            if (gm < Mr) {
                const float* p = A + (long)gm * K;
                if (gk + 3 < K) v = *reinterpret_cast<const float4*>(p + gk);
                else {
                    if (gk + 0 < K) v.x = p[gk + 0];
                    if (gk + 1 < K) v.y = p[gk + 1];
                    if (gk + 2 < K) v.z = p[gk + 2];
                }
            }
            As[a_k + 0][a_row] = v.x;
            As[a_k + 1][a_row] = v.y;
            As[a_k + 2][a_row] = v.z;
            As[a_k + 3][a_row] = v.w;
        }
        // ---- stage B tile ----
        if (BMODE == 0) {
            int gn = bm * 0 + bn + a_row, gk = k0 + a_k;  // same mapping as A
            float4 v = make_float4(-NEG, -NEG, -NEG, -NEG);
            if (gn < Nc) {
                const float* p = Bm + (long)gn * K;
                if (gk + 3 < K) v = *reinterpret_cast<const float4*>(p + gk);
                else {
                    if (gk + 0 < K) v.x = p[gk + 0];
                    if (gk + 1 < K) v.y = p[gk + 1];
                    if (gk + 2 < K) v.z = p[gk + 2];
                }
            }
            Bs[a_k + 0][a_row] = v.x;
            Bs[a_k + 1][a_row] = v.y;
            Bs[a_k + 2][a_row] = v.z;
            Bs[a_k + 3][a_row] = v.w;
        } else {
            int gk = k0 + bk_nn, gn = bn + bn_nn;
            float4 v = make_float4(-NEG, -NEG, -NEG, -NEG);
            if (gk < K) {
                const float* p = Bm + (long)gk * Nc;
                if (gn + 3 < Nc) v = *reinterpret_cast<const float4*>(p + gn);
                else {
                    if (gn + 0 < Nc) v.x = p[gn + 0];
                    if (gn + 1 < Nc) v.y = p[gn + 1];
                    if (gn + 2 < Nc) v.z = p[gn + 2];
                }
            }
            *reinterpret_cast<float4*>(&Bs[bk_nn][bn_nn]) = v;
        }
        __syncthreads();

#pragma unroll
        for (int kk = 0; kk < 16; kk++) {
            float4 a4 = *reinterpret_cast<const float4*>(&As[kk][ty << 2]);
            float4 b4 = *reinterpret_cast<const float4*>(&Bs[kk][tx << 2]);
            float ar[4] = {a4.x, a4.y, a4.z, a4.w};
            float br[4] = {b4.x, b4.y, b4.z, b4.w};
#pragma unroll
            for (int i = 0; i < 4; i++)
#pragma unroll
                for (int j = 0; j < 4; j++)
                    acc[i][j] = fmaxf(acc[i][j], ar[i] + br[j]);
        }
        __syncthreads();
    }

#pragma unroll
    for (int i = 0; i < 4; i++) {
        int gm = bm + (ty << 2) + i;
        if (gm >= Mr) continue;
#pragma unroll
        for (int j = 0; j < 4; j++) {
            int gn = bn + (tx << 2) + j;
            if (gn >= Nc) continue;
            float v = acc[i][j];
            if (epi == 1)      v += epi_ptr[(gm % Npat) * Nc + gn];
            else if (epi == 2) v = fmaxf(v, epi_ptr[0]);
            Cm[(long)gm * Nc + gn] = v;
        }
    }
}

// ---------------- per-row projective normalize (cols = 128) ----------------
__global__ void pnorm_rows(const float* __restrict__ X, float* __restrict__ Y, int rows) {
    int row = blockIdx.x * 8 + (threadIdx.x >> 5);
    if (row >= rows) return;
    int lane = threadIdx.x & 31;
    float4 v = reinterpret_cast<const float4*>(X + (long)row * D)[lane];
    float m = fmaxf(fmaxf(v.x, v.y), fmaxf(v.z, v.w));
#pragma unroll
    for (int o = 16; o; o >>= 1) m = fmaxf(m, __shfl_xor_sync(0xffffffffu, m, o));
    float4 r = make_float4(v.x - m, v.y - m, v.z - m, v.w - m);
    reinterpret_cast<float4*>(Y + (long)row * D)[lane] = r;
}

// --------- fused residual: h = max(h, pnorm(a)); optionally xn = pnorm(h) ---
__global__ void residual_norm(const float* __restrict__ Anew, float* __restrict__ H,
                              float* __restrict__ XN, int rows) {
    int row = blockIdx.x * 8 + (threadIdx.x >> 5);
    if (row >= rows) return;
    int lane = threadIdx.x & 31;
    float4 a = reinterpret_cast<const float4*>(Anew + (long)row * D)[lane];
    float m = fmaxf(fmaxf(a.x, a.y), fmaxf(a.z, a.w));
#pragma unroll
    for (int o = 16; o; o >>= 1) m = fmaxf(m, __shfl_xor_sync(0xffffffffu, m, o));
    float4 h = reinterpret_cast<const float4*>(H + (long)row * D)[lane];
    h.x = fmaxf(h.x, a.x - m); h.y = fmaxf(h.y, a.y - m);
    h.z = fmaxf(h.z, a.z - m); h.w = fmaxf(h.w, a.w - m);
    reinterpret_cast<float4*>(H + (long)row * D)[lane] = h;
    if (XN) {
        float m2 = fmaxf(fmaxf(h.x, h.y), fmaxf(h.z, h.w));
#pragma unroll
        for (int o = 16; o; o >>= 1) m2 = fmaxf(m2, __shfl_xor_sync(0xffffffffu, m2, o));
        float4 r = make_float4(h.x - m2, h.y - m2, h.z - m2, h.w - m2);
        reinterpret_cast<float4*>(XN + (long)row * D)[lane] = r;
    }
}

// ---------------- scores row-normalize (cols = 196) ------------------------
__global__ void rownorm196(float* __restrict__ S, int rows) {
    int row = blockIdx.x * 8 + (threadIdx.x >> 5);
    if (row >= rows) return;
    int lane = threadIdx.x & 31;
    float* p = S + (long)row * Npat;
    float vals[7];
    float m = -NEG;
#pragma unroll
    for (int i = 0; i < 7; i++) {
        int c = lane + 32 * i;
        if (c < Npat) { vals[i] = p[c]; m = fmaxf(m, vals[i]); }
    }
#pragma unroll
    for (int o = 16; o; o >>= 1) m = fmaxf(m, __shfl_xor_sync(0xffffffffu, m, o));
#pragma unroll
    for (int i = 0; i < 7; i++) {
        int c = lane + 32 * i;
        if (c < Npat) p[c] = vals[i] - m;
    }
}

// ---------------- global tropical pool over patches -------------------------
__global__ void pool_kernel(const float* __restrict__ H, float* __restrict__ Pl) {
    int b = blockIdx.x, d = threadIdx.x;
    float m = -NEG;
    const float* p = H + (long)b * Npat * D + d;
    for (int n = 0; n < Npat; n++) m = fmaxf(m, p[n * D]);
    Pl[b * D + d] = m;
}

// ---------------- head: logits[b,c] = max_d(pool[b,d]+W[c,d]) * ls ----------
__global__ void head_kernel(const float* __restrict__ Pl, const float* __restrict__ W,
                            const float* __restrict__ ls, float* __restrict__ out) {
    int w = blockIdx.x * 8 + (threadIdx.x >> 5);   // 8000 warps
    int lane = threadIdx.x & 31;
    int b = w / Cls, c = w % Cls;
    if (b >= Bsz) return;
    const float* p = Pl + b * D;
    const float* wr = W + (long)c * D;
    float m = -NEG;
#pragma unroll
    for (int k = 0; k < 4; k++) {
        int idx = lane + 32 * k;
        m = fmaxf(m, p[idx] + wr[idx]);
    }
#pragma unroll
    for (int o = 16; o; o >>= 1) m = fmaxf(m, __shfl_xor_sync(0xffffffffu, m, o));
    if (lane == 0) out[b * Cls + c] = m * ls[0];
}

// ---------------------------------------------------------------------------
extern "C" void kernel_launch(void* const* d_in, const int* in_sizes, int n_in,
                              void* d_out, int out_size) {
    const float* x       = (const float*)d_in[0];
    const float* embed_W = (const float*)d_in[1];
    const float* pos     = (const float*)d_in[2];
    const float* qW[2]  = {(const float*)d_in[3],  (const float*)d_in[9]};
    const float* kW[2]  = {(const float*)d_in[4],  (const float*)d_in[10]};
    const float* vW[2]  = {(const float*)d_in[5],  (const float*)d_in[11]};
    const float* f1W[2] = {(const float*)d_in[6],  (const float*)d_in[12]};
    const float* f2W[2] = {(const float*)d_in[7],  (const float*)d_in[13]};
    const float* tau[2] = {(const float*)d_in[8],  (const float*)d_in[14]};
    const float* headW  = (const float*)d_in[15];
    const float* ls     = (const float*)d_in[16];
    float* out = (float*)d_out;

    void *patches, *h, *xn, *q, *k, *v, *sc, *attn, *ffh, *ffo, *pool;
    cudaGetSymbolAddress(&patches, g_patches);
    cudaGetSymbolAddress(&h,    g_h);
    cudaGetSymbolAddress(&xn,   g_xn);
    cudaGetSymbolAddress(&q,    g_q);
    cudaGetSymbolAddress(&k,    g_k);
    cudaGetSymbolAddress(&v,    g_v);
    cudaGetSymbolAddress(&sc,   g_sc);
    cudaGetSymbolAddress(&attn, g_attn);
    cudaGetSymbolAddress(&ffh,  g_ffh);
    cudaGetSymbolAddress(&ffo,  g_ffo);
    cudaGetSymbolAddress(&pool, g_pool);

    float* fpat  = (float*)patches;
    float* fh    = (float*)h;
    float* fxn   = (float*)xn;
    float* fq    = (float*)q;
    float* fk    = (float*)k;
    float* fv    = (float*)v;
    float* fsc   = (float*)sc;
    float* fattn = (float*)attn;
    float* fffh  = (float*)ffh;
    float* fffo  = (float*)ffo;
    float* fpool = (float*)pool;

    patchify_kernel<<<Mrows, 256>>>(x, fpat);

    // embed + pos: (1568 x 128) = patches(1568x256) trop* embed_W(128x256)
    trop_gemm<0><<<dim3(25, 2, 1), 256>>>(fpat, embed_W, fh, Mrows, D, PD,
                                          0, 0, 0, 1, pos);

    for (int l = 0; l < 2; l++) {
        pnorm_rows<<<196, 256>>>(fh, fxn, Mrows);

        trop_gemm<0><<<dim3(25, 2, 1), 256>>>(fxn, qW[l], fq, Mrows, D, D, 0, 0, 0, 0, nullptr);
        trop_gemm<0><<<dim3(25, 2, 1), 256>>>(fxn, kW[l], fk, Mrows, D, D, 0, 0, 0, 0, nullptr);
        trop_gemm<0><<<dim3(25, 2, 1), 256>>>(fxn, vW[l], fv, Mrows, D, D, 0, 0, 0, 0, nullptr);

        // scores[b,i,j] = max_d q[b,i,d]+k[b,j,d]   (batched over z = 8)
        trop_gemm<0><<<dim3(4, 4, 8), 256>>>(fq, fk, fsc, Npat, Npat, D,
                                             (long)Npat * D, (long)Npat * D,
                                             (long)Npat * Npat, 0, nullptr);
        rownorm196<<<196, 256>>>(fsc, Mrows);

        // attn[b,i,d] = max_j scores[b,i,j] + v[b,j,d]   (B is [K][N] -> NN)
        trop_gemm<1><<<dim3(4, 2, 8), 256>>>(fsc, fv, fattn, Npat, D, Npat,
                                             (long)Npat * Npat, (long)Npat * D,
                                             (long)Npat * D, 0, nullptr);

        residual_norm<<<196, 256>>>(fattn, fh, fxn, Mrows);

        trop_gemm<0><<<dim3(25, 4, 1), 256>>>(fxn, f1W[l], fffh, Mrows, DFF, D,
                                              0, 0, 0, 2, tau[l]);
        trop_gemm<0><<<dim3(25, 2, 1), 256>>>(fffh, f2W[l], fffo, Mrows, D, DFF,
                                              0, 0, 0, 0, nullptr);

        residual_norm<<<196, 256>>>(fffo, fh, nullptr, Mrows);
    }

    pool_kernel<<<Bsz, D>>>(fh, fpool);
    head_kernel<<<1000, 256>>>(fpool, headW, ls, out);
}

// round 2
// speedup vs baseline: 1.5261x; 1.5261x over previous
#include <cuda_runtime.h>

#define NEG 1e30f

namespace {
constexpr int Bsz = 8;
constexpr int Npat = 196;
constexpr int PD  = 256;
constexpr int D   = 128;
constexpr int DFF = 256;
constexpr int Cls = 1000;
constexpr int Mrows = Bsz * Npat;  // 1568
}

// ---------------- scratch ----------------
__device__ float g_h   [Mrows * D];
__device__ float g_xn  [Mrows * D];
__device__ float g_qkv [3 * Mrows * D];
__device__ float g_sc  [Bsz * Npat * Npat];
__device__ float g_attn[Mrows * D];
__device__ float g_ffh [Mrows * DFF];
__device__ float g_ffo [Mrows * D];
__device__ float g_pool[Bsz * D];

// ---------------- tropical GEMM: 32x64 tile, 256 threads, 2x4 per thread ----
// BMODE 0: B[n*K+k] (TN).  BMODE 1: B[k*Nc+n] (NN).
// PATCH 1: A loaded directly from raw image (patchify fused), K must be 256.
// b1 != null => z in {0,1,2} selects b0/b1/b2 (qkv fusion); else Bm = b0 + z*bStride.
// epi: 0 none, 1 add pos[(gm%196)*Nc+gn], 2 max with epi_ptr[0]
template<int BMODE, int PATCH>
__global__ __launch_bounds__(256)
void trop_gemm(const float* __restrict__ A,
               const float* __restrict__ b0, const float* __restrict__ b1,
               const float* __restrict__ b2,
               float* __restrict__ Cm,
               int Mr, int Nc, int K,
               long aStride, long bStride, long cStride,
               int epi, const float* __restrict__ epi_ptr)
{
    const int z = blockIdx.z;
    const float* Bm = b1 ? (z == 0 ? b0 : (z == 1 ? b1 : b2))
                         : b0 + (long)z * bStride;
    A  += (long)z * aStride;
    Cm += (long)z * cStride;

    __shared__ float As[16][32];
    __shared__ float Bs[16][64];

    const int bm = blockIdx.x * 32;
    const int bn = blockIdx.y * 64;
    const int tid = threadIdx.x;
    const int ty2 = (tid >> 4) << 1;     // row pair 0..30
    const int tx4 = (tid & 15) << 2;     // col quad 0..60

    // --- per-thread staging coordinates (fixed across k-tiles) ---
    const int a_row = tid >> 3;          // 0..31
    const int a_k   = (tid & 7) << 1;    // 0,2,..,14
    const int gm_a  = bm + a_row;
    const float* a_src = nullptr;
    if (PATCH) {
        int b  = gm_a / Npat, n = gm_a % Npat;
        int gy = n / 14, gx = n % 14;
        int py0 = a_k >> 4;              // always 0 (a_k <= 14)
        int px  = a_k & 15;
        a_src = A + (long)b * 224 * 224 + (long)(gy * 16 + py0) * 224 + gx * 16 + px;
    } else {
        a_src = A + (long)gm_a * K;
    }

    // BMODE0 staging coords
    const int b_n = tid >> 2;            // 0..63
    const int b_k = (tid & 3) << 2;      // 0,4,8,12
    const int gn_b = bn + b_n;
    const float* b_src0 = Bm + (long)gn_b * K;
    // BMODE1 staging coords
    const int b1_k = tid >> 4;           // 0..15
    const int b1_n = (tid & 15) << 2;    // 0..60

    float acc[2][4];
#pragma unroll
    for (int i = 0; i < 2; i++)
#pragma unroll
        for (int j = 0; j < 4; j++) acc[i][j] = -NEG;

    for (int k0 = 0; k0 < K; k0 += 16) {
        // ---- stage A ----
        {
            float2 v = make_float2(-NEG, -NEG);
            if (gm_a < Mr) {
                if (PATCH) {
                    v = *reinterpret_cast<const float2*>(a_src + (k0 >> 4) * 224);
                } else {
                    int gk = k0 + a_k;
                    if (gk + 1 < K) v = *reinterpret_cast<const float2*>(a_src + gk);
                    else if (gk < K) v.x = a_src[gk];
                }
            }
            As[a_k + 0][a_row] = v.x;
            As[a_k + 1][a_row] = v.y;
        }
        // ---- stage B ----
        if (BMODE == 0) {
            int gk = k0 + b_k;
            float4 v = make_float4(-NEG, -NEG, -NEG, -NEG);
            if (gn_b < Nc) {
                if (gk + 3 < K) v = *reinterpret_cast<const float4*>(b_src0 + gk);
                else {
                    if (gk + 0 < K) v.x = b_src0[gk + 0];
                    if (gk + 1 < K) v.y = b_src0[gk + 1];
                    if (gk + 2 < K) v.z = b_src0[gk + 2];
                }
            }
            Bs[b_k + 0][b_n] = v.x;
            Bs[b_k + 1][b_n] = v.y;
            Bs[b_k + 2][b_n] = v.z;
            Bs[b_k + 3][b_n] = v.w;
        } else {
            int gk = k0 + b1_k, gn = bn + b1_n;
            float4 v = make_float4(-NEG, -NEG, -NEG, -NEG);
            if (gk < K) {
                const float* p = Bm + (long)gk * Nc;
                if (gn + 3 < Nc) v = *reinterpret_cast<const float4*>(p + gn);
                else {
                    if (gn + 0 < Nc) v.x = p[gn + 0];
                    if (gn + 1 < Nc) v.y = p[gn + 1];
                    if (gn + 2 < Nc) v.z = p[gn + 2];
                }
            }
            *reinterpret_cast<float4*>(&Bs[b1_k][b1_n]) = v;
        }
        __syncthreads();

#pragma unroll
        for (int kk = 0; kk < 16; kk++) {
            float2 a = *reinterpret_cast<const float2*>(&As[kk][ty2]);
            float4 b = *reinterpret_cast<const float4*>(&Bs[kk][tx4]);
            acc[0][0] = fmaxf(acc[0][0], a.x + b.x);
            acc[0][1] = fmaxf(acc[0][1], a.x + b.y);
            acc[0][2] = fmaxf(acc[0][2], a.x + b.z);
            acc[0][3] = fmaxf(acc[0][3], a.x + b.w);
            acc[1][0] = fmaxf(acc[1][0], a.y + b.x);
            acc[1][1] = fmaxf(acc[1][1], a.y + b.y);
            acc[1][2] = fmaxf(acc[1][2], a.y + b.z);
            acc[1][3] = fmaxf(acc[1][3], a.y + b.w);
        }
        __syncthreads();
    }

#pragma unroll
    for (int i = 0; i < 2; i++) {
        int gm = bm + ty2 + i;
        if (gm >= Mr) continue;
#pragma unroll
        for (int j = 0; j < 4; j++) {
            int gn = bn + tx4 + j;
            if (gn >= Nc) continue;
            float v = acc[i][j];
            if (epi == 1)      v += epi_ptr[(gm % Npat) * Nc + gn];
            else if (epi == 2) v = fmaxf(v, epi_ptr[0]);
            Cm[(long)gm * Nc + gn] = v;
        }
    }
}

// ---------------- per-row projective normalize (cols = 128) ----------------
__global__ void pnorm_rows(const float* __restrict__ X, float* __restrict__ Y, int rows) {
    int row = blockIdx.x * 8 + (threadIdx.x >> 5);
    if (row >= rows) return;
    int lane = threadIdx.x & 31;
    float4 v = reinterpret_cast<const float4*>(X + (long)row * D)[lane];
    float m = fmaxf(fmaxf(v.x, v.y), fmaxf(v.z, v.w));
#pragma unroll
    for (int o = 16; o; o >>= 1) m = fmaxf(m, __shfl_xor_sync(0xffffffffu, m, o));
    float4 r = make_float4(v.x - m, v.y - m, v.z - m, v.w - m);
    reinterpret_cast<float4*>(Y + (long)row * D)[lane] = r;
}

// --------- fused residual: h = max(h, pnorm(a)); optionally xn = pnorm(h) ---
__global__ void residual_norm(const float* __restrict__ Anew, float* __restrict__ H,
                              float* __restrict__ XN, int rows) {
    int row = blockIdx.x * 8 + (threadIdx.x >> 5);
    if (row >= rows) return;
    int lane = threadIdx.x & 31;
    float4 a = reinterpret_cast<const float4*>(Anew + (long)row * D)[lane];
    float m = fmaxf(fmaxf(a.x, a.y), fmaxf(a.z, a.w));
#pragma unroll
    for (int o = 16; o; o >>= 1) m = fmaxf(m, __shfl_xor_sync(0xffffffffu, m, o));
    float4 h = reinterpret_cast<const float4*>(H + (long)row * D)[lane];
    h.x = fmaxf(h.x, a.x - m); h.y = fmaxf(h.y, a.y - m);
    h.z = fmaxf(h.z, a.z - m); h.w = fmaxf(h.w, a.w - m);
    reinterpret_cast<float4*>(H + (long)row * D)[lane] = h;
    if (XN) {
        float m2 = fmaxf(fmaxf(h.x, h.y), fmaxf(h.z, h.w));
#pragma unroll
        for (int o = 16; o; o >>= 1) m2 = fmaxf(m2, __shfl_xor_sync(0xffffffffu, m2, o));
        float4 r = make_float4(h.x - m2, h.y - m2, h.z - m2, h.w - m2);
        reinterpret_cast<float4*>(XN + (long)row * D)[lane] = r;
    }
}

// ---------------- scores row-normalize (cols = 196) ------------------------
__global__ void rownorm196(float* __restrict__ S, int rows) {
    int row = blockIdx.x * 8 + (threadIdx.x >> 5);
    if (row >= rows) return;
    int lane = threadIdx.x & 31;
    float* p = S + (long)row * Npat;
    float vals[7];
    float m = -NEG;
#pragma unroll
    for (int i = 0; i < 7; i++) {
        int c = lane + 32 * i;
        if (c < Npat) { vals[i] = p[c]; m = fmaxf(m, vals[i]); }
    }
#pragma unroll
    for (int o = 16; o; o >>= 1) m = fmaxf(m, __shfl_xor_sync(0xffffffffu, m, o));
#pragma unroll
    for (int i = 0; i < 7; i++) {
        int c = lane + 32 * i;
        if (c < Npat) p[c] = vals[i] - m;
    }
}

// ---------------- global tropical pool over patches -------------------------
__global__ void pool_kernel(const float* __restrict__ H, float* __restrict__ Pl) {
    int b = blockIdx.x, d = threadIdx.x;
    float m = -NEG;
    const float* p = H + (long)b * Npat * D + d;
    for (int n = 0; n < Npat; n++) m = fmaxf(m, p[n * D]);
    Pl[b * D + d] = m;
}

// ---------------- head ------------------------------------------------------
__global__ void head_kernel(const float* __restrict__ Pl, const float* __restrict__ W,
                            const float* __restrict__ ls, float* __restrict__ out) {
    int w = blockIdx.x * 8 + (threadIdx.x >> 5);
    int lane = threadIdx.x & 31;
    int b = w / Cls, c = w % Cls;
    if (b >= Bsz) return;
    const float* p = Pl + b * D;
    const float* wr = W + (long)c * D;
    float m = -NEG;
#pragma unroll
    for (int k = 0; k < 4; k++) {
        int idx = lane + 32 * k;
        m = fmaxf(m, p[idx] + wr[idx]);
    }
#pragma unroll
    for (int o = 16; o; o >>= 1) m = fmaxf(m, __shfl_xor_sync(0xffffffffu, m, o));
    if (lane == 0) out[b * Cls + c] = m * ls[0];
}

// ---------------------------------------------------------------------------
extern "C" void kernel_launch(void* const* d_in, const int* in_sizes, int n_in,
                              void* d_out, int out_size) {
    const float* x       = (const float*)d_in[0];
    const float* embed_W = (const float*)d_in[1];
    const float* pos     = (const float*)d_in[2];
    const float* qW[2]  = {(const float*)d_in[3],  (const float*)d_in[9]};
    const float* kW[2]  = {(const float*)d_in[4],  (const float*)d_in[10]};
    const float* vW[2]  = {(const float*)d_in[5],  (const float*)d_in[11]};
    const float* f1W[2] = {(const float*)d_in[6],  (const float*)d_in[12]};
    const float* f2W[2] = {(const float*)d_in[7],  (const float*)d_in[13]};
    const float* tau[2] = {(const float*)d_in[8],  (const float*)d_in[14]};
    const float* headW  = (const float*)d_in[15];
    const float* ls     = (const float*)d_in[16];
    float* out = (float*)d_out;

    void *h, *xn, *qkv, *sc, *attn, *ffh, *ffo, *pool;
    cudaGetSymbolAddress(&h,    g_h);
    cudaGetSymbolAddress(&xn,   g_xn);
    cudaGetSymbolAddress(&qkv,  g_qkv);
    cudaGetSymbolAddress(&sc,   g_sc);
    cudaGetSymbolAddress(&attn, g_attn);
    cudaGetSymbolAddress(&ffh,  g_ffh);
    cudaGetSymbolAddress(&ffo,  g_ffo);
    cudaGetSymbolAddress(&pool, g_pool);

    float* fh    = (float*)h;
    float* fxn   = (float*)xn;
    float* fq    = (float*)qkv;                      // [0]
    float* fk    = fq + (long)Mrows * D;             // [1]
    float* fv    = fq + 2L * Mrows * D;              // [2]
    float* fsc   = (float*)sc;
    float* fattn = (float*)attn;
    float* fffh  = (float*)ffh;
    float* fffo  = (float*)ffo;
    float* fpool = (float*)pool;

    // embed (patchify fused) + pos:  (1568 x 128) from image, K=256
    trop_gemm<0, 1><<<dim3(49, 2, 1), 256>>>(x, embed_W, nullptr, nullptr, fh,
                                             Mrows, D, PD, 0, 0, 0, 1, pos);
    pnorm_rows<<<196, 256>>>(fh, fxn, Mrows);

    for (int l = 0; l < 2; l++) {
        // fused q/k/v: z selects weight, output strided into g_qkv
        trop_gemm<0, 0><<<dim3(49, 2, 3), 256>>>(fxn, qW[l], kW[l], vW[l], fq,
                                                 Mrows, D, D,
                                                 0, 0, (long)Mrows * D, 0, nullptr);

        // scores[b,i,j] = max_d q[b,i,d]+k[b,j,d]
        trop_gemm<0, 0><<<dim3(7, 4, 8), 256>>>(fq, fk, nullptr, nullptr, fsc,
                                                Npat, Npat, D,
                                                (long)Npat * D, (long)Npat * D,
                                                (long)Npat * Npat, 0, nullptr);
        rownorm196<<<196, 256>>>(fsc, Mrows);

        // attn[b,i,d] = max_j scores[b,i,j] + v[b,j,d]
        trop_gemm<1, 0><<<dim3(7, 2, 8), 256>>>(fsc, fv, nullptr, nullptr, fattn,
                                                Npat, D, Npat,
                                                (long)Npat * Npat, (long)Npat * D,
                                                (long)Npat * D, 0, nullptr);

        residual_norm<<<196, 256>>>(fattn, fh, fxn, Mrows);

        trop_gemm<0, 0><<<dim3(49, 4, 1), 256>>>(fxn, f1W[l], nullptr, nullptr, fffh,
                                                 Mrows, DFF, D, 0, 0, 0, 2, tau[l]);
        trop_gemm<0, 0><<<dim3(49, 2, 1), 256>>>(fffh, f2W[l], nullptr, nullptr, fffo,
                                                 Mrows, D, DFF, 0, 0, 0, 0, nullptr);

        // emit xn for the next layer's first pnorm (saves a launch)
        residual_norm<<<196, 256>>>(fffo, fh, (l == 0) ? fxn : nullptr, Mrows);
    }

    pool_kernel<<<Bsz, D>>>(fh, fpool);
    head_kernel<<<1000, 256>>>(fpool, headW, ls, out);
}

// round 3
// speedup vs baseline: 1.7726x; 1.1615x over previous
#include <cuda_runtime.h>

#define NEG 1e30f

namespace {
constexpr int Bsz = 8;
constexpr int Npat = 196;
constexpr int PD  = 256;
constexpr int D   = 128;
constexpr int DFF = 256;
constexpr int Cls = 1000;
constexpr int Mrows = Bsz * Npat;  // 1568
}

// ---------------- scratch ----------------
__device__ float g_h   [Mrows * D];
__device__ float g_xn  [Mrows * D];
__device__ float g_qkv [3 * Mrows * D];
__device__ float g_sc  [Bsz * Npat * Npat];
__device__ float g_attn[Mrows * D];
__device__ float g_ffh [Mrows * DFF];
__device__ float g_ffo [Mrows * D];
__device__ float g_pool[Bsz * D];

// ============ tropical GEMM: MTx64 tile, 128 threads, double-buffered =======
// C[m,n] = max_k (A[m,k] + B[.,.])
// BMODE 0: B[n*K+k] (TN).  BMODE 1: B[k*Nc+n] (NN).
// PATCH 1: A loaded directly from raw image (patchify fused), K == 256.
// b1 != null => z selects b0/b1/b2 (qkv fusion); else Bm = b0 + z*bStride.
// epi: 0 none, 1 add pos[(gm%196)*Nc+gn..], 2 max with epi_ptr[0] (tau)
// Requires: K % 4 == 0, Nc % 4 == 0.
template<int BMODE, int PATCH, int MT>
__global__ __launch_bounds__(128)
void trop_gemm(const float* __restrict__ A,
               const float* __restrict__ b0, const float* __restrict__ b1,
               const float* __restrict__ b2,
               float* __restrict__ Cm,
               int Mr, int Nc, int K,
               long aStride, long bStride, long cStride,
               int epi, const float* __restrict__ epi_ptr)
{
    constexpr int AR = MT / 8;  // rows per thread (4 or 2)
    const int z = blockIdx.z;
    const float* Bm = b1 ? (z == 0 ? b0 : (z == 1 ? b1 : b2))
                         : b0 + (long)z * bStride;
    if (!PATCH) A += (long)z * aStride;
    Cm += (long)z * cStride;

    __shared__ float As[2][16][MT];
    __shared__ float Bs[2][16][64];

    const int bm = blockIdx.x * MT;
    const int bn = blockIdx.y * 64;
    const int tid = threadIdx.x;
    const int ty = tid >> 4;       // 0..7
    const int tx = tid & 15;       // 0..15

    // ---- A staging coords (STS bank == lane id -> conflict-free-ish) ----
    int a_row, a_k;
    bool a_do;
    if (MT == 32) { a_row = tid & 31; a_k = (tid >> 5) << 2; a_do = true; }
    else          { a_row = tid & 15; a_k = ((tid >> 4) & 3) << 2; a_do = (tid < 64); }
    const int gm_a = bm + a_row;
    const bool a_valid = a_do && (gm_a < Mr);
    const float* a_src;
    if (PATCH) {
        int b  = gm_a / 196, n = gm_a % 196;
        int gy = n / 14, gx = n % 14;
        a_src = A + (long)b * 224 * 224 + (long)(gy * 16) * 224 + gx * 16 + a_k;
    } else {
        a_src = A + (long)gm_a * K + a_k;
    }

    // ---- B staging coords ----
    const int b_n  = tid & 63;            // BMODE0
    const int b_k8 = (tid >> 6) << 3;
    const bool b_valid0 = (bn + b_n) < Nc;
    const float* b_src0 = Bm + (long)(bn + b_n) * K + b_k8;
    const int b_k1 = tid >> 3;            // BMODE1: 0..15
    const int b_n8 = (tid & 7) << 3;
    const float* b_src1 = Bm + (long)b_k1 * Nc + bn + b_n8;

    float acc[AR][4];
#pragma unroll
    for (int i = 0; i < AR; i++)
#pragma unroll
        for (int j = 0; j < 4; j++) acc[i][j] = -NEG;

    const int ntiles = (K + 15) >> 4;

    float4 ra, rb0, rb1;
    auto gload = [&](int t) {
        const int k0 = t << 4;
        ra = rb0 = rb1 = make_float4(-NEG, -NEG, -NEG, -NEG);
        if (a_valid && (PATCH || (k0 + a_k < K))) {
            if (PATCH) ra = *reinterpret_cast<const float4*>(a_src + t * 224);
            else       ra = *reinterpret_cast<const float4*>(a_src + k0);
        }
        if (BMODE == 0) {
            if (b_valid0) {
                if (k0 + b_k8 < K)     rb0 = *reinterpret_cast<const float4*>(b_src0 + k0);
                if (k0 + b_k8 + 4 < K) rb1 = *reinterpret_cast<const float4*>(b_src0 + k0 + 4);
            }
        } else {
            if (k0 + b_k1 < K) {
                const float* p = b_src1 + (long)k0 * Nc;
                rb0 = *reinterpret_cast<const float4*>(p);
                rb1 = *reinterpret_cast<const float4*>(p + 4);
            }
        }
    };
    auto sts = [&](int buf) {
        if (a_do) {
            As[buf][a_k + 0][a_row] = ra.x;
            As[buf][a_k + 1][a_row] = ra.y;
            As[buf][a_k + 2][a_row] = ra.z;
            As[buf][a_k + 3][a_row] = ra.w;
        }
        if (BMODE == 0) {
            Bs[buf][b_k8 + 0][b_n] = rb0.x;
            Bs[buf][b_k8 + 1][b_n] = rb0.y;
            Bs[buf][b_k8 + 2][b_n] = rb0.z;
            Bs[buf][b_k8 + 3][b_n] = rb0.w;
            Bs[buf][b_k8 + 4][b_n] = rb1.x;
            Bs[buf][b_k8 + 5][b_n] = rb1.y;
            Bs[buf][b_k8 + 6][b_n] = rb1.z;
            Bs[buf][b_k8 + 7][b_n] = rb1.w;
        } else {
            *reinterpret_cast<float4*>(&Bs[buf][b_k1][b_n8])     = rb0;
            *reinterpret_cast<float4*>(&Bs[buf][b_k1][b_n8 + 4]) = rb1;
        }
    };

    gload(0);
    sts(0);
    __syncthreads();

    for (int t = 0; t < ntiles; t++) {
        const int cur = t & 1;
        const bool more = (t + 1 < ntiles);
        if (more) gload(t + 1);
#pragma unroll
        for (int kk = 0; kk < 16; kk++) {
            float a[AR];
            if (MT == 32) {
                float4 av = *reinterpret_cast<const float4*>(&As[cur][kk][ty << 2]);
                a[0] = av.x; a[1] = av.y; a[2] = av.z; a[3] = av.w;
            } else {
                float2 av = *reinterpret_cast<const float2*>(&As[cur][kk][ty << 1]);
                a[0] = av.x; a[1] = av.y;
            }
            float4 bv = *reinterpret_cast<const float4*>(&Bs[cur][kk][tx << 2]);
#pragma unroll
            for (int i = 0; i < AR; i++) {
                acc[i][0] = fmaxf(acc[i][0], a[i] + bv.x);
                acc[i][1] = fmaxf(acc[i][1], a[i] + bv.y);
                acc[i][2] = fmaxf(acc[i][2], a[i] + bv.z);
                acc[i][3] = fmaxf(acc[i][3], a[i] + bv.w);
            }
        }
        if (more) { sts((t + 1) & 1); __syncthreads(); }
    }

    const float tauv = (epi == 2) ? epi_ptr[0] : 0.f;
#pragma unroll
    for (int i = 0; i < AR; i++) {
        int gm = bm + ty * AR + i;
        if (gm >= Mr) continue;
        int gn = bn + (tx << 2);
        float4 v = make_float4(acc[i][0], acc[i][1], acc[i][2], acc[i][3]);
        if (epi == 1) {
            float4 p = *reinterpret_cast<const float4*>(&epi_ptr[(long)(gm % 196) * Nc + gn]);
            v.x += p.x; v.y += p.y; v.z += p.z; v.w += p.w;
        } else if (epi == 2) {
            v.x = fmaxf(v.x, tauv); v.y = fmaxf(v.y, tauv);
            v.z = fmaxf(v.z, tauv); v.w = fmaxf(v.w, tauv);
        }
        float* dst = Cm + (long)gm * Nc + gn;
        if (gn + 3 < Nc) {
            *reinterpret_cast<float4*>(dst) = v;
        } else {
            float vv[4] = {v.x, v.y, v.z, v.w};
            for (int e = 0; e < 4; e++)
                if (gn + e < Nc) dst[e] = vv[e];
        }
    }
}

// ---------------- per-row projective normalize (cols = 128) ----------------
__global__ void pnorm_rows(const float* __restrict__ X, float* __restrict__ Y, int rows) {
    int row = blockIdx.x * 8 + (threadIdx.x >> 5);
    if (row >= rows) return;
    int lane = threadIdx.x & 31;
    float4 v = reinterpret_cast<const float4*>(X + (long)row * D)[lane];
    float m = fmaxf(fmaxf(v.x, v.y), fmaxf(v.z, v.w));
#pragma unroll
    for (int o = 16; o; o >>= 1) m = fmaxf(m, __shfl_xor_sync(0xffffffffu, m, o));
    float4 r = make_float4(v.x - m, v.y - m, v.z - m, v.w - m);
    reinterpret_cast<float4*>(Y + (long)row * D)[lane] = r;
}

// --------- fused residual: h = max(h, pnorm(a)); optionally xn = pnorm(h) ---
__global__ void residual_norm(const float* __restrict__ Anew, float* __restrict__ H,
                              float* __restrict__ XN, int rows) {
    int row = blockIdx.x * 8 + (threadIdx.x >> 5);
    if (row >= rows) return;
    int lane = threadIdx.x & 31;
    float4 a = reinterpret_cast<const float4*>(Anew + (long)row * D)[lane];
    float m = fmaxf(fmaxf(a.x, a.y), fmaxf(a.z, a.w));
#pragma unroll
    for (int o = 16; o; o >>= 1) m = fmaxf(m, __shfl_xor_sync(0xffffffffu, m, o));
    float4 h = reinterpret_cast<const float4*>(H + (long)row * D)[lane];
    h.x = fmaxf(h.x, a.x - m); h.y = fmaxf(h.y, a.y - m);
    h.z = fmaxf(h.z, a.z - m); h.w = fmaxf(h.w, a.w - m);
    reinterpret_cast<float4*>(H + (long)row * D)[lane] = h;
    if (XN) {
        float m2 = fmaxf(fmaxf(h.x, h.y), fmaxf(h.z, h.w));
#pragma unroll
        for (int o = 16; o; o >>= 1) m2 = fmaxf(m2, __shfl_xor_sync(0xffffffffu, m2, o));
        float4 r = make_float4(h.x - m2, h.y - m2, h.z - m2, h.w - m2);
        reinterpret_cast<float4*>(XN + (long)row * D)[lane] = r;
    }
}

// ---------------- global tropical pool over patches -------------------------
__global__ void pool_kernel(const float* __restrict__ H, float* __restrict__ Pl) {
    int b = blockIdx.x, d = threadIdx.x;
    float m = -NEG;
    const float* p = H + (long)b * Npat * D + d;
    for (int n = 0; n < Npat; n++) m = fmaxf(m, p[n * D]);
    Pl[b * D + d] = m;
}

// ---------------- head ------------------------------------------------------
__global__ void head_kernel(const float* __restrict__ Pl, const float* __restrict__ W,
                            const float* __restrict__ ls, float* __restrict__ out) {
    int w = blockIdx.x * 8 + (threadIdx.x >> 5);
    int lane = threadIdx.x & 31;
    int b = w / Cls, c = w % Cls;
    if (b >= Bsz) return;
    const float* p = Pl + b * D;
    const float* wr = W + (long)c * D;
    float m = -NEG;
#pragma unroll
    for (int k = 0; k < 4; k++) {
        int idx = lane + 32 * k;
        m = fmaxf(m, p[idx] + wr[idx]);
    }
#pragma unroll
    for (int o = 16; o; o >>= 1) m = fmaxf(m, __shfl_xor_sync(0xffffffffu, m, o));
    if (lane == 0) out[b * Cls + c] = m * ls[0];
}

// ---------------------------------------------------------------------------
extern "C" void kernel_launch(void* const* d_in, const int* in_sizes, int n_in,
                              void* d_out, int out_size) {
    const float* x       = (const float*)d_in[0];
    const float* embed_W = (const float*)d_in[1];
    const float* pos     = (const float*)d_in[2];
    const float* qW[2]  = {(const float*)d_in[3],  (const float*)d_in[9]};
    const float* kW[2]  = {(const float*)d_in[4],  (const float*)d_in[10]};
    const float* vW[2]  = {(const float*)d_in[5],  (const float*)d_in[11]};
    const float* f1W[2] = {(const float*)d_in[6],  (const float*)d_in[12]};
    const float* f2W[2] = {(const float*)d_in[7],  (const float*)d_in[13]};
    const float* tau[2] = {(const float*)d_in[8],  (const float*)d_in[14]};
    const float* headW  = (const float*)d_in[15];
    const float* ls     = (const float*)d_in[16];
    float* out = (float*)d_out;

    void *h, *xn, *qkv, *sc, *attn, *ffh, *ffo, *pool;
    cudaGetSymbolAddress(&h,    g_h);
    cudaGetSymbolAddress(&xn,   g_xn);
    cudaGetSymbolAddress(&qkv,  g_qkv);
    cudaGetSymbolAddress(&sc,   g_sc);
    cudaGetSymbolAddress(&attn, g_attn);
    cudaGetSymbolAddress(&ffh,  g_ffh);
    cudaGetSymbolAddress(&ffo,  g_ffo);
    cudaGetSymbolAddress(&pool, g_pool);

    float* fh    = (float*)h;
    float* fxn   = (float*)xn;
    float* fq    = (float*)qkv;
    float* fk    = fq + (long)Mrows * D;
    float* fv    = fq + 2L * Mrows * D;
    float* fsc   = (float*)sc;
    float* fattn = (float*)attn;
    float* fffh  = (float*)ffh;
    float* fffo  = (float*)ffo;
    float* fpool = (float*)pool;

    const long NpD = (long)Npat * D;
    const long NpN = (long)Npat * Npat;

    // embed (patchify fused) + pos
    trop_gemm<0, 1, 16><<<dim3(98, 2, 1), 128>>>(x, embed_W, nullptr, nullptr, fh,
                                                 Mrows, D, PD, 0, 0, 0, 1, pos);
    pnorm_rows<<<196, 256>>>(fh, fxn, Mrows);

    for (int l = 0; l < 2; l++) {
        // fused q/k/v
        trop_gemm<0, 0, 32><<<dim3(49, 2, 3), 128>>>(fxn, qW[l], kW[l], vW[l], fq,
                                                     Mrows, D, D,
                                                     0, 0, (long)Mrows * D, 0, nullptr);
        // scores (unnormalized — rownorm cancels under later pnorm)
        trop_gemm<0, 0, 16><<<dim3(13, 4, 8), 128>>>(fq, fk, nullptr, nullptr, fsc,
                                                     Npat, Npat, D,
                                                     NpD, NpD, NpN, 0, nullptr);
        // attn out
        trop_gemm<1, 0, 16><<<dim3(13, 2, 8), 128>>>(fsc, fv, nullptr, nullptr, fattn,
                                                     Npat, D, Npat,
                                                     NpN, NpD, NpD, 0, nullptr);
        residual_norm<<<196, 256>>>(fattn, fh, fxn, Mrows);

        trop_gemm<0, 0, 16><<<dim3(98, 4, 1), 128>>>(fxn, f1W[l], nullptr, nullptr, fffh,
                                                     Mrows, DFF, D, 0, 0, 0, 2, tau[l]);
        trop_gemm<0, 0, 16><<<dim3(98, 2, 1), 128>>>(fffh, f2W[l], nullptr, nullptr, fffo,
                                                     Mrows, D, DFF, 0, 0, 0, 0, nullptr);
        residual_norm<<<196, 256>>>(fffo, fh, (l == 0) ? fxn : nullptr, Mrows);
    }

    pool_kernel<<<Bsz, D>>>(fh, fpool);
    head_kernel<<<1000, 256>>>(fpool, headW, ls, out);
}

// round 5
// speedup vs baseline: 2.0817x; 1.1744x over previous
#include <cuda_runtime.h>

#define NEG 1e30f

namespace {
constexpr int Bsz = 8;
constexpr int Npat = 196;
constexpr int D   = 128;
constexpr int DFF = 256;
constexpr int Cls = 1000;
constexpr int Mrows = Bsz * Npat;          // 1568
constexpr long MD   = (long)Mrows * D;     // 200704
constexpr long NpD  = (long)Npat * D;
constexpr long NpN  = (long)Npat * Npat;
}

// ---------------- scratch ----------------
__device__ float g_h   [Mrows * D];
__device__ float g_xn  [Mrows * D];
__device__ float g_qkv [3 * Mrows * D];
__device__ float g_sc  [2 * Bsz * Npat * Npat];   // 2 K-split partials
__device__ float g_attn[2 * Mrows * D];           // embed partials, then attn partials
__device__ float g_ffh [2 * Mrows * DFF];
__device__ float g_ffo [2 * Mrows * D];
__device__ float g_pool[Bsz * D];

// ======== tropical GEMM: 32x64 tile, 128 thr, 4x4/thread, double-buffer =====
// C[m,n] = max_k (A[m,k] + B)     BMODE0: B[n*K+k]; BMODE1: B[k*Nc+n]
// PATCH: A read from raw image (patchify fused, K=256, kChunk mult of 16)
// KSPLIT: blockIdx.z = batch*KSPLIT + s; split s covers k in [s*kChunk, ...)
// A2: A := max(A, Aalt) elementwise (combine upstream K-split partials)
// epi: 0 none, 1 +pos[(gm%196)*Nc+gn], 2 max with epi_ptr[0]
template<int BMODE, int PATCH, int KSPLIT, int A2>
__global__ __launch_bounds__(128)
void trop_gemm(const float* __restrict__ A, const float* __restrict__ Aalt,
               const float* __restrict__ b0, const float* __restrict__ b1,
               const float* __restrict__ b2,
               float* __restrict__ Cm,
               int Mr, int Nc, int K,
               long aStride, long bStride, long cStride, long splitStride,
               int kChunk, int epi, const float* __restrict__ epi_ptr)
{
    const int z = blockIdx.z;
    const int batch = (KSPLIT == 1) ? z : z / KSPLIT;
    const int s     = (KSPLIT == 1) ? 0 : z % KSPLIT;
    const int kBase = s * kChunk;
    const int kLen  = min(K - kBase, kChunk);

    const float* Bm = b1 ? (batch == 0 ? b0 : (batch == 1 ? b1 : b2))
                         : b0 + (long)batch * bStride;
    Cm += (long)batch * cStride + (long)s * splitStride;

    __shared__ float As[2][16][32];
    __shared__ float Bs[2][16][64];

    const int bm = blockIdx.x * 32;
    const int bn = blockIdx.y * 64;
    const int tid = threadIdx.x;
    const int ty = tid >> 4;       // 0..7  (4 rows each)
    const int tx = tid & 15;       // 0..15 (4 cols each)

    // ---- A staging: 1 float4 per thread ----
    const int a_row = tid & 31;
    const int a_k   = (tid >> 5) << 2;           // 0,4,8,12
    const int gm_a  = bm + a_row;
    const bool a_valid = (gm_a < Mr);
    const float* a_src;
    const float* a_src2 = nullptr;
    if (PATCH) {
        int b  = gm_a / 196, n = gm_a % 196;
        int gy = n / 14, gx = n % 14;
        a_src = A + (long)b * 224 * 224 + (long)(gy * 16 + (kBase >> 4)) * 224 + gx * 16 + a_k;
    } else {
        long off = (long)batch * aStride + (long)gm_a * K + kBase + a_k;
        a_src = A + off;
        if (A2) a_src2 = Aalt + off;
    }

    // ---- B staging ----
    const int b_n  = tid & 63;                   // BMODE0: 2 float4 along k
    const int b_k8 = (tid >> 6) << 3;
    const bool b_valid0 = (bn + b_n) < Nc;
    const float* b_src0 = Bm + (long)(bn + b_n) * K + kBase + b_k8;
    const int b_k1 = tid >> 3;                   // BMODE1
    const int b_n8 = (tid & 7) << 3;
    const float* b_src1 = Bm + (long)(kBase + b_k1) * Nc + bn + b_n8;

    float acc[4][4];
#pragma unroll
    for (int i = 0; i < 4; i++)
#pragma unroll
        for (int j = 0; j < 4; j++) acc[i][j] = -NEG;

    const int ntiles = (kLen + 15) >> 4;

    float4 ra, rb0, rb1;
    auto gload = [&](int t) {
        const int k0 = t << 4;
        ra = rb0 = rb1 = make_float4(-NEG, -NEG, -NEG, -NEG);
        if (a_valid && (PATCH || (k0 + a_k < kLen))) {
            if (PATCH) {
                ra = *reinterpret_cast<const float4*>(a_src + t * 224);
            } else {
                ra = *reinterpret_cast<const float4*>(a_src + k0);
                if (A2) {
                    float4 r2 = *reinterpret_cast<const float4*>(a_src2 + k0);
                    ra.x = fmaxf(ra.x, r2.x); ra.y = fmaxf(ra.y, r2.y);
                    ra.z = fmaxf(ra.z, r2.z); ra.w = fmaxf(ra.w, r2.w);
                }
            }
        }
        if (BMODE == 0) {
            if (b_valid0) {
                if (k0 + b_k8 < kLen)     rb0 = *reinterpret_cast<const float4*>(b_src0 + k0);
                if (k0 + b_k8 + 4 < kLen) rb1 = *reinterpret_cast<const float4*>(b_src0 + k0 + 4);
            }
        } else {
            if (k0 + b_k1 < kLen) {
                const float* p = b_src1 + (long)k0 * Nc;
                rb0 = *reinterpret_cast<const float4*>(p);
                rb1 = *reinterpret_cast<const float4*>(p + 4);
            }
        }
    };
    auto sts = [&](int buf) {
        As[buf][a_k + 0][a_row] = ra.x;
        As[buf][a_k + 1][a_row] = ra.y;
        As[buf][a_k + 2][a_row] = ra.z;
        As[buf][a_k + 3][a_row] = ra.w;
        if (BMODE == 0) {
            Bs[buf][b_k8 + 0][b_n] = rb0.x;
            Bs[buf][b_k8 + 1][b_n] = rb0.y;
            Bs[buf][b_k8 + 2][b_n] = rb0.z;
            Bs[buf][b_k8 + 3][b_n] = rb0.w;
            Bs[buf][b_k8 + 4][b_n] = rb1.x;
            Bs[buf][b_k8 + 5][b_n] = rb1.y;
            Bs[buf][b_k8 + 6][b_n] = rb1.z;
            Bs[buf][b_k8 + 7][b_n] = rb1.w;
        } else {
            *reinterpret_cast<float4*>(&Bs[buf][b_k1][b_n8])     = rb0;
            *reinterpret_cast<float4*>(&Bs[buf][b_k1][b_n8 + 4]) = rb1;
        }
    };

    gload(0);
    sts(0);
    __syncthreads();

    for (int t = 0; t < ntiles; t++) {
        const int cur = t & 1;
        const bool more = (t + 1 < ntiles);
        if (more) gload(t + 1);
#pragma unroll
        for (int kk = 0; kk < 16; kk++) {
            float4 av = *reinterpret_cast<const float4*>(&As[cur][kk][ty << 2]);
            float4 bv = *reinterpret_cast<const float4*>(&Bs[cur][kk][tx << 2]);
            float a[4] = {av.x, av.y, av.z, av.w};
#pragma unroll
            for (int i = 0; i < 4; i++) {
                acc[i][0] = fmaxf(acc[i][0], a[i] + bv.x);
                acc[i][1] = fmaxf(acc[i][1], a[i] + bv.y);
                acc[i][2] = fmaxf(acc[i][2], a[i] + bv.z);
                acc[i][3] = fmaxf(acc[i][3], a[i] + bv.w);
            }
        }
        if (more) { sts((t + 1) & 1); __syncthreads(); }
    }

    const float tauv = (epi == 2) ? epi_ptr[0] : 0.f;
#pragma unroll
    for (int i = 0; i < 4; i++) {
        int gm = bm + (ty << 2) + i;
        if (gm >= Mr) continue;
        int gn = bn + (tx << 2);
        if (gn >= Nc) continue;
        float4 v = make_float4(acc[i][0], acc[i][1], acc[i][2], acc[i][3]);
        if (epi == 1) {
            float4 p = *reinterpret_cast<const float4*>(&epi_ptr[(long)(gm % 196) * Nc + gn]);
            v.x += p.x; v.y += p.y; v.z += p.z; v.w += p.w;
        } else if (epi == 2) {
            v.x = fmaxf(v.x, tauv); v.y = fmaxf(v.y, tauv);
            v.z = fmaxf(v.z, tauv); v.w = fmaxf(v.w, tauv);
        }
        *reinterpret_cast<float4*>(Cm + (long)gm * Nc + gn) = v;
    }
}

// -------- embed combine: h = max(a0,a1); xn = pnorm(h) ----------------------
__global__ void embed_combine(const float* __restrict__ A0, const float* __restrict__ A1,
                              float* __restrict__ H, float* __restrict__ XN, int rows) {
    int row = blockIdx.x * 8 + (threadIdx.x >> 5);
    if (row >= rows) return;
    int lane = threadIdx.x & 31;
    float4 a = reinterpret_cast<const float4*>(A0 + (long)row * D)[lane];
    float4 b = reinterpret_cast<const float4*>(A1 + (long)row * D)[lane];
    a.x = fmaxf(a.x, b.x); a.y = fmaxf(a.y, b.y);
    a.z = fmaxf(a.z, b.z); a.w = fmaxf(a.w, b.w);
    reinterpret_cast<float4*>(H + (long)row * D)[lane] = a;
    float m = fmaxf(fmaxf(a.x, a.y), fmaxf(a.z, a.w));
#pragma unroll
    for (int o = 16; o; o >>= 1) m = fmaxf(m, __shfl_xor_sync(0xffffffffu, m, o));
    float4 r = make_float4(a.x - m, a.y - m, a.z - m, a.w - m);
    reinterpret_cast<float4*>(XN + (long)row * D)[lane] = r;
}

// --- residual2: a = max(a0,a1); h = max(h, pnorm(a)); optional xn = pnorm(h) -
__global__ void residual2(const float* __restrict__ A0, const float* __restrict__ A1,
                          float* __restrict__ H, float* __restrict__ XN, int rows) {
    int row = blockIdx.x * 8 + (threadIdx.x >> 5);
    if (row >= rows) return;
    int lane = threadIdx.x & 31;
    float4 a = reinterpret_cast<const float4*>(A0 + (long)row * D)[lane];
    float4 b = reinterpret_cast<const float4*>(A1 + (long)row * D)[lane];
    a.x = fmaxf(a.x, b.x); a.y = fmaxf(a.y, b.y);
    a.z = fmaxf(a.z, b.z); a.w = fmaxf(a.w, b.w);
    float m = fmaxf(fmaxf(a.x, a.y), fmaxf(a.z, a.w));
#pragma unroll
    for (int o = 16; o; o >>= 1) m = fmaxf(m, __shfl_xor_sync(0xffffffffu, m, o));
    float4 h = reinterpret_cast<const float4*>(H + (long)row * D)[lane];
    h.x = fmaxf(h.x, a.x - m); h.y = fmaxf(h.y, a.y - m);
    h.z = fmaxf(h.z, a.z - m); h.w = fmaxf(h.w, a.w - m);
    reinterpret_cast<float4*>(H + (long)row * D)[lane] = h;
    if (XN) {
        float m2 = fmaxf(fmaxf(h.x, h.y), fmaxf(h.z, h.w));
#pragma unroll
        for (int o = 16; o; o >>= 1) m2 = fmaxf(m2, __shfl_xor_sync(0xffffffffu, m2, o));
        float4 r = make_float4(h.x - m2, h.y - m2, h.z - m2, h.w - m2);
        reinterpret_cast<float4*>(XN + (long)row * D)[lane] = r;
    }
}

// ---------------- global tropical pool over patches -------------------------
__global__ void pool_kernel(const float* __restrict__ H, float* __restrict__ Pl) {
    int b = blockIdx.x, d = threadIdx.x;
    float m = -NEG;
    const float* p = H + (long)b * Npat * D + d;
    for (int n = 0; n < Npat; n++) m = fmaxf(m, p[n * D]);
    Pl[b * D + d] = m;
}

// ---------------- head ------------------------------------------------------
__global__ void head_kernel(const float* __restrict__ Pl, const float* __restrict__ W,
                            const float* __restrict__ ls, float* __restrict__ out) {
    int w = blockIdx.x * 8 + (threadIdx.x >> 5);
    int lane = threadIdx.x & 31;
    int b = w / Cls, c = w % Cls;
    if (b >= Bsz) return;
    const float* p = Pl + b * D;
    const float* wr = W + (long)c * D;
    float m = -NEG;
#pragma unroll
    for (int k = 0; k < 4; k++) {
        int idx = lane + 32 * k;
        m = fmaxf(m, p[idx] + wr[idx]);
    }
#pragma unroll
    for (int o = 16; o; o >>= 1) m = fmaxf(m, __shfl_xor_sync(0xffffffffu, m, o));
    if (lane == 0) out[b * Cls + c] = m * ls[0];
}

// ---------------------------------------------------------------------------
extern "C" void kernel_launch(void* const* d_in, const int* in_sizes, int n_in,
                              void* d_out, int out_size) {
    const float* x       = (const float*)d_in[0];
    const float* embed_W = (const float*)d_in[1];
    const float* pos     = (const float*)d_in[2];
    const float* qW[2]  = {(const float*)d_in[3],  (const float*)d_in[9]};
    const float* kW[2]  = {(const float*)d_in[4],  (const float*)d_in[10]};
    const float* vW[2]  = {(const float*)d_in[5],  (const float*)d_in[11]};
    const float* f1W[2] = {(const float*)d_in[6],  (const float*)d_in[12]};
    const float* f2W[2] = {(const float*)d_in[7],  (const float*)d_in[13]};
    const float* tau[2] = {(const float*)d_in[8],  (const float*)d_in[14]};
    const float* headW  = (const float*)d_in[15];
    const float* ls     = (const float*)d_in[16];
    float* out = (float*)d_out;

    void *h, *xn, *qkv, *sc, *attn, *ffh, *ffo, *pool;
    cudaGetSymbolAddress(&h,    g_h);
    cudaGetSymbolAddress(&xn,   g_xn);
    cudaGetSymbolAddress(&qkv,  g_qkv);
    cudaGetSymbolAddress(&sc,   g_sc);
    cudaGetSymbolAddress(&attn, g_attn);
    cudaGetSymbolAddress(&ffh,  g_ffh);
    cudaGetSymbolAddress(&ffo,  g_ffo);
    cudaGetSymbolAddress(&pool, g_pool);

    float* fh    = (float*)h;
    float* fxn   = (float*)xn;
    float* fq    = (float*)qkv;
    float* fk    = fq + MD;
    float* fv    = fq + 2 * MD;
    float* fsc   = (float*)sc;
    float* fattn = (float*)attn;
    float* fffh  = (float*)ffh;
    float* fffo  = (float*)ffo;
    float* fpool = (float*)pool;

    // embed (patchify fused, K=256 split 2) -> partials in g_attn
    trop_gemm<0, 1, 2, 0><<<dim3(49, 2, 2), 128>>>(
        x, nullptr, embed_W, nullptr, nullptr, fattn,
        Mrows, D, 256, 0, 0, 0, MD, 128, 1, pos);
    embed_combine<<<196, 256>>>(fattn, fattn + MD, fh, fxn, Mrows);

    for (int l = 0; l < 2; l++) {
        // fused q/k/v (z = batch selects weight)
        trop_gemm<0, 0, 1, 0><<<dim3(49, 2, 3), 128>>>(
            fxn, nullptr, qW[l], kW[l], vW[l], fq,
            Mrows, D, D, 0, 0, MD, 0, D, 0, nullptr);

        // scores, K=128 split 2 -> partials (combined in attn-out A staging)
        trop_gemm<0, 0, 2, 0><<<dim3(7, 4, 16), 128>>>(
            fq, nullptr, fk, nullptr, nullptr, fsc,
            Npat, Npat, D, NpD, NpD, NpN, (long)Bsz * NpN, 64, 0, nullptr);

        // attn-out, A = max(sc0, sc1), K=196 split (112, 84) -> partials
        trop_gemm<1, 0, 2, 1><<<dim3(7, 2, 16), 128>>>(
            fsc, fsc + Bsz * NpN, fv, nullptr, nullptr, fattn,
            Npat, D, Npat, NpN, NpD, NpD, MD, 112, 0, nullptr);

        residual2<<<196, 256>>>(fattn, fattn + MD, fh, fxn, Mrows);

        // ff1, K=128 split 2 -> partials (tau epilogue distributes over max)
        trop_gemm<0, 0, 2, 0><<<dim3(49, 4, 2), 128>>>(
            fxn, nullptr, f1W[l], nullptr, nullptr, fffh,
            Mrows, DFF, D, 0, 0, 0, (long)Mrows * DFF, 64, 2, tau[l]);

        // ff2, A = max(ffh0, ffh1), K=256 split 2 -> partials
        trop_gemm<0, 0, 2, 1><<<dim3(49, 2, 2), 128>>>(
            fffh, fffh + (long)Mrows * DFF, f2W[l], nullptr, nullptr, fffo,
            Mrows, D, DFF, 0, 0, 0, MD, 128, 0, nullptr);

        residual2<<<196, 256>>>(fffo, fffo + MD, fh, (l == 0) ? fxn : nullptr, Mrows);
    }

    pool_kernel<<<Bsz, D>>>(fh, fpool);
    head_kernel<<<1000, 256>>>(fpool, headW, ls, out);
}

// round 7
// speedup vs baseline: 2.1270x; 1.0218x over previous
#include <cuda_runtime.h>

#define NEG 1e30f

namespace {
constexpr int Bsz = 8;
constexpr int Npat = 196;
constexpr int D   = 128;
constexpr int DFF = 256;
constexpr int Cls = 1000;
constexpr int Mrows = Bsz * Npat;          // 1568
constexpr long MD    = (long)Mrows * D;    // 200704
constexpr long MDFF  = (long)Mrows * DFF;  // 401408
constexpr long NpD   = (long)Npat * D;
constexpr long NpN   = (long)Npat * Npat;
}

// ---------------- scratch ----------------
__device__ float g_h   [Mrows * D];
__device__ float g_xn  [Mrows * D];
__device__ float g_qkv [6 * Mrows * D];           // q0,q1,k0,k1,v0,v1
__device__ float g_sc  [4 * Bsz * Npat * Npat];   // 4 K-split partials
__device__ float g_attn[4 * Mrows * D];           // embed/attn partials
__device__ float g_ffh [4 * Mrows * DFF];
__device__ float g_ffo [4 * Mrows * D];
__device__ float g_pool[Bsz * D];

// ======== tropical GEMM: 32x64 tile, 128 thr, 4x4/thread, double-buffer =====
// C[m,n] = max_k (A[m,k] + B)     BMODE0: B[n*K+k]; BMODE1: B[k*Nc+n]
// PATCH: A read from raw image (patchify fused; kChunk mult of 16)
// KSPLIT: blockIdx.z = batch*KSPLIT + s; split s covers k in [s*kChunk, ...)
// ACMB/BCMB: combine that many upstream K-split partials (strides aPart/bPart)
// epi: 0 none, 1 +pos[(gm%196)*Nc+gn], 2 max with epi_ptr[0]
template<int BMODE, int PATCH, int KSPLIT, int ACMB, int BCMB>
__global__ __launch_bounds__(128)
void trop_gemm(const float* __restrict__ A,
               const float* __restrict__ b0, const float* __restrict__ b1,
               const float* __restrict__ b2,
               float* __restrict__ Cm,
               int Mr, int Nc, int K,
               long aStride, long bStride, long cStride, long splitStride,
               long aPart, long bPart,
               int kChunk, int epi, const float* __restrict__ epi_ptr)
{
    const int z = blockIdx.z;
    const int batch = (KSPLIT == 1) ? z : z / KSPLIT;
    const int s     = (KSPLIT == 1) ? 0 : z % KSPLIT;
    const int kBase = s * kChunk;
    const int kLen  = min(K - kBase, kChunk);

    const float* Bm = b1 ? (batch == 0 ? b0 : (batch == 1 ? b1 : b2))
                         : b0 + (long)batch * bStride;
    Cm += (long)batch * cStride + (long)s * splitStride;

    __shared__ float As[2][16][32];
    __shared__ float Bs[2][16][64];

    const int bm = blockIdx.x * 32;
    const int bn = blockIdx.y * 64;
    const int tid = threadIdx.x;
    const int ty = tid >> 4;
    const int tx = tid & 15;

    // ---- A staging: 1 float4 per thread (x ACMB partials) ----
    const int a_row = tid & 31;
    const int a_k   = (tid >> 5) << 2;
    const int gm_a  = bm + a_row;
    const bool a_valid = (gm_a < Mr);
    const float* a_src;
    if (PATCH) {
        int b  = gm_a / 196, n = gm_a % 196;
        int gy = n / 14, gx = n % 14;
        a_src = A + (long)b * 224 * 224 + (long)(gy * 16 + (kBase >> 4)) * 224 + gx * 16 + a_k;
    } else {
        a_src = A + (long)batch * aStride + (long)gm_a * K + kBase + a_k;
    }

    // ---- B staging ----
    const int b_n  = tid & 63;
    const int b_k8 = (tid >> 6) << 3;
    const bool b_valid0 = (bn + b_n) < Nc;
    const float* b_src0 = Bm + (long)(bn + b_n) * K + kBase + b_k8;
    const int b_k1 = tid >> 3;
    const int b_n8 = (tid & 7) << 3;
    const float* b_src1 = Bm + (long)(kBase + b_k1) * Nc + bn + b_n8;

    float acc[4][4];
#pragma unroll
    for (int i = 0; i < 4; i++)
#pragma unroll
        for (int j = 0; j < 4; j++) acc[i][j] = -NEG;

    const int ntiles = (kLen + 15) >> 4;

    float4 ra, rb0, rb1;
    auto fmax4 = [](float4& a, float4 b) {
        a.x = fmaxf(a.x, b.x); a.y = fmaxf(a.y, b.y);
        a.z = fmaxf(a.z, b.z); a.w = fmaxf(a.w, b.w);
    };
    auto gload = [&](int t) {
        const int k0 = t << 4;
        ra = rb0 = rb1 = make_float4(-NEG, -NEG, -NEG, -NEG);
        if (a_valid && (PATCH || (k0 + a_k < kLen))) {
            if (PATCH) {
                ra = *reinterpret_cast<const float4*>(a_src + t * 224);
            } else {
                ra = *reinterpret_cast<const float4*>(a_src + k0);
#pragma unroll
                for (int c = 1; c < ACMB; c++)
                    fmax4(ra, *reinterpret_cast<const float4*>(a_src + c * aPart + k0));
            }
        }
        if (BMODE == 0) {
            if (b_valid0) {
                if (k0 + b_k8 < kLen) {
                    rb0 = *reinterpret_cast<const float4*>(b_src0 + k0);
#pragma unroll
                    for (int c = 1; c < BCMB; c++)
                        fmax4(rb0, *reinterpret_cast<const float4*>(b_src0 + c * bPart + k0));
                }
                if (k0 + b_k8 + 4 < kLen) {
                    rb1 = *reinterpret_cast<const float4*>(b_src0 + k0 + 4);
#pragma unroll
                    for (int c = 1; c < BCMB; c++)
                        fmax4(rb1, *reinterpret_cast<const float4*>(b_src0 + c * bPart + k0 + 4));
                }
            }
        } else {
            if (k0 + b_k1 < kLen) {
                const float* p = b_src1 + (long)k0 * Nc;
                rb0 = *reinterpret_cast<const float4*>(p);
                rb1 = *reinterpret_cast<const float4*>(p + 4);
#pragma unroll
                for (int c = 1; c < BCMB; c++) {
                    fmax4(rb0, *reinterpret_cast<const float4*>(p + c * bPart));
                    fmax4(rb1, *reinterpret_cast<const float4*>(p + c * bPart + 4));
                }
            }
        }
    };
    auto sts = [&](int buf) {
        As[buf][a_k + 0][a_row] = ra.x;
        As[buf][a_k + 1][a_row] = ra.y;
        As[buf][a_k + 2][a_row] = ra.z;
        As[buf][a_k + 3][a_row] = ra.w;
        if (BMODE == 0) {
            Bs[buf][b_k8 + 0][b_n] = rb0.x;
            Bs[buf][b_k8 + 1][b_n] = rb0.y;
            Bs[buf][b_k8 + 2][b_n] = rb0.z;
            Bs[buf][b_k8 + 3][b_n] = rb0.w;
            Bs[buf][b_k8 + 4][b_n] = rb1.x;
            Bs[buf][b_k8 + 5][b_n] = rb1.y;
            Bs[buf][b_k8 + 6][b_n] = rb1.z;
            Bs[buf][b_k8 + 7][b_n] = rb1.w;
        } else {
            *reinterpret_cast<float4*>(&Bs[buf][b_k1][b_n8])     = rb0;
            *reinterpret_cast<float4*>(&Bs[buf][b_k1][b_n8 + 4]) = rb1;
        }
    };

    gload(0);
    sts(0);
    __syncthreads();

    for (int t = 0; t < ntiles; t++) {
        const int cur = t & 1;
        const bool more = (t + 1 < ntiles);
        if (more) gload(t + 1);

        // 2-stage register pipeline over k-steps: prefetch kk+1 while doing kk
        float4 av = *reinterpret_cast<const float4*>(&As[cur][0][ty << 2]);
        float4 bv = *reinterpret_cast<const float4*>(&Bs[cur][0][tx << 2]);
#pragma unroll
        for (int kk = 0; kk < 16; kk++) {
            float4 avn, bvn;
            if (kk < 15) {
                avn = *reinterpret_cast<const float4*>(&As[cur][kk + 1][ty << 2]);
                bvn = *reinterpret_cast<const float4*>(&Bs[cur][kk + 1][tx << 2]);
            }
            float a[4] = {av.x, av.y, av.z, av.w};
#pragma unroll
            for (int i = 0; i < 4; i++) {
                acc[i][0] = fmaxf(acc[i][0], a[i] + bv.x);
                acc[i][1] = fmaxf(acc[i][1], a[i] + bv.y);
                acc[i][2] = fmaxf(acc[i][2], a[i] + bv.z);
                acc[i][3] = fmaxf(acc[i][3], a[i] + bv.w);
            }
            if (kk < 15) { av = avn; bv = bvn; }
        }
        if (more) { sts((t + 1) & 1); __syncthreads(); }
    }

    const float tauv = (epi == 2) ? epi_ptr[0] : 0.f;
#pragma unroll
    for (int i = 0; i < 4; i++) {
        int gm = bm + (ty << 2) + i;
        if (gm >= Mr) continue;
        int gn = bn + (tx << 2);
        if (gn >= Nc) continue;
        float4 v = make_float4(acc[i][0], acc[i][1], acc[i][2], acc[i][3]);
        if (epi == 1) {
            float4 p = *reinterpret_cast<const float4*>(&epi_ptr[(long)(gm % 196) * Nc + gn]);
            v.x += p.x; v.y += p.y; v.z += p.z; v.w += p.w;
        } else if (epi == 2) {
            v.x = fmaxf(v.x, tauv); v.y = fmaxf(v.y, tauv);
            v.z = fmaxf(v.z, tauv); v.w = fmaxf(v.w, tauv);
        }
        *reinterpret_cast<float4*>(Cm + (long)gm * Nc + gn) = v;
    }
}

// ------ embed combine: h = max of 4 partials; xn = pnorm(h) -----------------
__global__ void embed_combine4(const float* __restrict__ A, long stride,
                               float* __restrict__ H, float* __restrict__ XN, int rows) {
    int row = blockIdx.x * 8 + (threadIdx.x >> 5);
    if (row >= rows) return;
    int lane = threadIdx.x & 31;
    long off = (long)row * D;
    float4 a = reinterpret_cast<const float4*>(A + off)[lane];
#pragma unroll
    for (int c = 1; c < 4; c++) {
        float4 b = reinterpret_cast<const float4*>(A + c * stride + off)[lane];
        a.x = fmaxf(a.x, b.x); a.y = fmaxf(a.y, b.y);
        a.z = fmaxf(a.z, b.z); a.w = fmaxf(a.w, b.w);
    }
    reinterpret_cast<float4*>(H + off)[lane] = a;
    float m = fmaxf(fmaxf(a.x, a.y), fmaxf(a.z, a.w));
#pragma unroll
    for (int o = 16; o; o >>= 1) m = fmaxf(m, __shfl_xor_sync(0xffffffffu, m, o));
    float4 r = make_float4(a.x - m, a.y - m, a.z - m, a.w - m);
    reinterpret_cast<float4*>(XN + off)[lane] = r;
}

// --- residual4: a = max of 4 partials; h = max(h, pnorm(a)); opt xn=pnorm(h) -
__global__ void residual4(const float* __restrict__ A, long stride,
                          float* __restrict__ H, float* __restrict__ XN, int rows) {
    int row = blockIdx.x * 8 + (threadIdx.x >> 5);
    if (row >= rows) return;
    int lane = threadIdx.x & 31;
    long off = (long)row * D;
    float4 a = reinterpret_cast<const float4*>(A + off)[lane];
#pragma unroll
    for (int c = 1; c < 4; c++) {
        float4 b = reinterpret_cast<const float4*>(A + c * stride + off)[lane];
        a.x = fmaxf(a.x, b.x); a.y = fmaxf(a.y, b.y);
        a.z = fmaxf(a.z, b.z); a.w = fmaxf(a.w, b.w);
    }
    float m = fmaxf(fmaxf(a.x, a.y), fmaxf(a.z, a.w));
#pragma unroll
    for (int o = 16; o; o >>= 1) m = fmaxf(m, __shfl_xor_sync(0xffffffffu, m, o));
    float4 h = reinterpret_cast<const float4*>(H + off)[lane];
    h.x = fmaxf(h.x, a.x - m); h.y = fmaxf(h.y, a.y - m);
    h.z = fmaxf(h.z, a.z - m); h.w = fmaxf(h.w, a.w - m);
    reinterpret_cast<float4*>(H + off)[lane] = h;
    if (XN) {
        float m2 = fmaxf(fmaxf(h.x, h.y), fmaxf(h.z, h.w));
#pragma unroll
        for (int o = 16; o; o >>= 1) m2 = fmaxf(m2, __shfl_xor_sync(0xffffffffu, m2, o));
        float4 r = make_float4(h.x - m2, h.y - m2, h.z - m2, h.w - m2);
        reinterpret_cast<float4*>(XN + off)[lane] = r;
    }
}

// ---------------- global tropical pool over patches -------------------------
__global__ void pool_kernel(const float* __restrict__ H, float* __restrict__ Pl) {
    int b = blockIdx.x, d = threadIdx.x;
    float m = -NEG;
    const float* p = H + (long)b * Npat * D + d;
    for (int n = 0; n < Npat; n++) m = fmaxf(m, p[n * D]);
    Pl[b * D + d] = m;
}

// ---------------- head ------------------------------------------------------
__global__ void head_kernel(const float* __restrict__ Pl, const float* __restrict__ W,
                            const float* __restrict__ ls, float* __restrict__ out) {
    int w = blockIdx.x * 8 + (threadIdx.x >> 5);
    int lane = threadIdx.x & 31;
    int b = w / Cls, c = w % Cls;
    if (b >= Bsz) return;
    const float* p = Pl + b * D;
    const float* wr = W + (long)c * D;
    float m = -NEG;
#pragma unroll
    for (int k = 0; k < 4; k++) {
        int idx = lane + 32 * k;
        m = fmaxf(m, p[idx] + wr[idx]);
    }
#pragma unroll
    for (int o = 16; o; o >>= 1) m = fmaxf(m, __shfl_xor_sync(0xffffffffu, m, o));
    if (lane == 0) out[b * Cls + c] = m * ls[0];
}

// ---------------------------------------------------------------------------
extern "C" void kernel_launch(void* const* d_in, const int* in_sizes, int n_in,
                              void* d_out, int out_size) {
    const float* x       = (const float*)d_in[0];
    const float* embed_W = (const float*)d_in[1];
    const float* pos     = (const float*)d_in[2];
    const float* qW[2]  = {(const float*)d_in[3],  (const float*)d_in[9]};
    const float* kW[2]  = {(const float*)d_in[4],  (const float*)d_in[10]};
    const float* vW[2]  = {(const float*)d_in[5],  (const float*)d_in[11]};
    const float* f1W[2] = {(const float*)d_in[6],  (const float*)d_in[12]};
    const float* f2W[2] = {(const float*)d_in[7],  (const float*)d_in[13]};
    const float* tau[2] = {(const float*)d_in[8],  (const float*)d_in[14]};
    const float* headW  = (const float*)d_in[15];
    const float* ls     = (const float*)d_in[16];
    float* out = (float*)d_out;

    void *h, *xn, *qkv, *sc, *attn, *ffh, *ffo, *pool;
    cudaGetSymbolAddress(&h,    g_h);
    cudaGetSymbolAddress(&xn,   g_xn);
    cudaGetSymbolAddress(&qkv,  g_qkv);
    cudaGetSymbolAddress(&sc,   g_sc);
    cudaGetSymbolAddress(&attn, g_attn);
    cudaGetSymbolAddress(&ffh,  g_ffh);
    cudaGetSymbolAddress(&ffo,  g_ffo);
    cudaGetSymbolAddress(&pool, g_pool);

    float* fh    = (float*)h;
    float* fxn   = (float*)xn;
    float* fq    = (float*)qkv;          // q partials [0,1]·MD
    float* fk    = fq + 2 * MD;          // k partials [2,3]·MD
    float* fv    = fq + 4 * MD;          // v partials [4,5]·MD
    float* fsc   = (float*)sc;
    float* fattn = (float*)attn;
    float* fffh  = (float*)ffh;
    float* fffo  = (float*)ffo;
    float* fpool = (float*)pool;

    // embed (patchify fused, K=256 split 4) -> 4 partials in g_attn
    trop_gemm<0, 1, 4, 1, 1><<<dim3(49, 2, 4), 128>>>(
        x, embed_W, nullptr, nullptr, fattn,
        Mrows, D, 256, 0, 0, 0, MD, 0, 0, 64, 1, pos);
    embed_combine4<<<196, 256>>>(fattn, MD, fh, fxn, Mrows);

    for (int l = 0; l < 2; l++) {
        // fused q/k/v, K=128 split 2 -> 2 partials each
        trop_gemm<0, 0, 2, 1, 1><<<dim3(49, 2, 6), 128>>>(
            fxn, qW[l], kW[l], vW[l], fq,
            Mrows, D, D, 0, 0, 2 * MD, MD, 0, 0, 64, 0, nullptr);

        // scores, combine q/k partials at staging; K=128 split 4
        trop_gemm<0, 0, 4, 2, 2><<<dim3(7, 4, 32), 128>>>(
            fq, fk, nullptr, nullptr, fsc,
            Npat, Npat, D, NpD, NpD, NpN, (long)Bsz * NpN, MD, MD, 32, 0, nullptr);

        // attn-out: A = max of 4 score partials, B = max of 2 v partials; K=196 split 4
        trop_gemm<1, 0, 4, 4, 2><<<dim3(7, 2, 32), 128>>>(
            fsc, fv, nullptr, nullptr, fattn,
            Npat, D, Npat, NpN, NpD, NpD, MD, (long)Bsz * NpN, MD, 52, 0, nullptr);

        residual4<<<196, 256>>>(fattn, MD, fh, fxn, Mrows);

        // ff1, K=128 split 4 -> 4 partials (tau epilogue distributes over max)
        trop_gemm<0, 0, 4, 1, 1><<<dim3(49, 4, 4), 128>>>(
            fxn, f1W[l], nullptr, nullptr, fffh,
            Mrows, DFF, D, 0, 0, 0, MDFF, 0, 0, 32, 2, tau[l]);

        // ff2: A = max of 4 ffh partials; K=256 split 4
        trop_gemm<0, 0, 4, 4, 1><<<dim3(49, 2, 4), 128>>>(
            fffh, f2W[l], nullptr, nullptr, fffo,
            Mrows, D, DFF, 0, 0, 0, MD, MDFF, 0, 64, 0, nullptr);

        residual4<<<196, 256>>>(fffo, MD, fh, (l == 0) ? fxn : nullptr, Mrows);
    }

    pool_kernel<<<Bsz, D>>>(fh, fpool);
    head_kernel<<<1000, 256>>>(fpool, headW, ls, out);
}

// round 12
// speedup vs baseline: 2.2743x; 1.0693x over previous
#include <cuda_runtime.h>

#define NEG 1e30f

namespace {
constexpr int Bsz = 8;
constexpr int Npat = 196;
constexpr int D   = 128;
constexpr int DFF = 256;
constexpr int Cls = 1000;
constexpr int Mrows = Bsz * Npat;          // 1568
constexpr long MD    = (long)Mrows * D;    // 200704
constexpr long MDFF  = (long)Mrows * DFF;  // 401408
constexpr long NpD   = (long)Npat * D;
constexpr long NpN   = (long)Npat * Npat;
}

// ---------------- scratch ----------------
__device__ float g_h   [Mrows * D];
__device__ float g_xn  [Mrows * D];
__device__ float g_qkv [6 * Mrows * D];           // q0,q1,k0,k1,v0,v1
__device__ float g_sc  [4 * Bsz * Npat * Npat];   // 4 K-split partials
__device__ float g_attn[4 * Mrows * D];           // embed/attn partials
__device__ float g_ffh [4 * Mrows * DFF];
__device__ float g_ffo [4 * Mrows * D];
__device__ float g_pool[Bsz * D];

// ---------------- packed f32x2 helpers (sm_100+) ----------------------------
__device__ __forceinline__ unsigned long long pack2(float a) {
    unsigned long long r;
    asm("mov.b64 %0, {%1, %1};" : "=l"(r) : "f"(a));
    return r;
}
// (aclo, achi) = max((aclo, achi), a2 + b2)  -- packed add, scalar maxes
__device__ __forceinline__ void addmax2(float& aclo, float& achi,
                                        unsigned long long a2, unsigned long long b2) {
    asm("{\n\t"
        ".reg .b64 t;\n\t"
        ".reg .f32 l, h;\n\t"
        "add.rn.f32x2 t, %2, %3;\n\t"
        "mov.b64 {l, h}, t;\n\t"
        "max.f32 %0, %0, l;\n\t"
        "max.f32 %1, %1, h;\n\t"
        "}" : "+f"(aclo), "+f"(achi) : "l"(a2), "l"(b2));
}

// ======== tropical GEMM: 32x64 tile, 128 thr, 4x4/thread, double-buffer =====
// C[m,n] = max_k (A[m,k] + B)     BMODE0: B[n*K+k]; BMODE1: B[k*Nc+n]
// PATCH: A read from raw image (patchify fused; kChunk mult of 16)
// KSPLIT: blockIdx.z = batch*KSPLIT + s; split s covers k in [s*kChunk, ...)
// ACMB/BCMB: combine that many upstream K-split partials (strides aPart/bPart)
// epi: 0 none, 1 +pos[(gm%196)*Nc+gn], 2 max with epi_ptr[0]
template<int BMODE, int PATCH, int KSPLIT, int ACMB, int BCMB>
__global__ __launch_bounds__(128)
void trop_gemm(const float* __restrict__ A,
               const float* __restrict__ b0, const float* __restrict__ b1,
               const float* __restrict__ b2,
               float* __restrict__ Cm,
               int Mr, int Nc, int K,
               long aStride, long bStride, long cStride, long splitStride,
               long aPart, long bPart,
               int kChunk, int epi, const float* __restrict__ epi_ptr)
{
    const int z = blockIdx.z;
    const int batch = (KSPLIT == 1) ? z : z / KSPLIT;
    const int s     = (KSPLIT == 1) ? 0 : z % KSPLIT;
    const int kBase = s * kChunk;
    const int kLen  = min(K - kBase, kChunk);

    const float* Bm = b1 ? (batch == 0 ? b0 : (batch == 1 ? b1 : b2))
                         : b0 + (long)batch * bStride;
    Cm += (long)batch * cStride + (long)s * splitStride;

    __shared__ float As[2][16][32];
    __shared__ float Bs[2][16][64];

    const int bm = blockIdx.x * 32;
    const int bn = blockIdx.y * 64;
    const int tid = threadIdx.x;
    const int ty = tid >> 4;
    const int tx = tid & 15;

    // ---- A staging: 1 float4 per thread (x ACMB partials) ----
    const int a_row = tid & 31;
    const int a_k   = (tid >> 5) << 2;
    const int gm_a  = bm + a_row;
    const bool a_valid = (gm_a < Mr);
    const float* a_src;
    if (PATCH) {
        int b  = gm_a / 196, n = gm_a % 196;
        int gy = n / 14, gx = n % 14;
        a_src = A + (long)b * 224 * 224 + (long)(gy * 16 + (kBase >> 4)) * 224 + gx * 16 + a_k;
    } else {
        a_src = A + (long)batch * aStride + (long)gm_a * K + kBase + a_k;
    }

    // ---- B staging ----
    const int b_n  = tid & 63;
    const int b_k8 = (tid >> 6) << 3;
    const bool b_valid0 = (bn + b_n) < Nc;
    const float* b_src0 = Bm + (long)(bn + b_n) * K + kBase + b_k8;
    const int b_k1 = tid >> 3;
    const int b_n8 = (tid & 7) << 3;
    const float* b_src1 = Bm + (long)(kBase + b_k1) * Nc + bn + b_n8;

    float acc[4][4];
#pragma unroll
    for (int i = 0; i < 4; i++)
#pragma unroll
        for (int j = 0; j < 4; j++) acc[i][j] = -NEG;

    const int ntiles = (kLen + 15) >> 4;

    float4 ra, rb0, rb1;
    auto fmax4 = [](float4& a, float4 b) {
        a.x = fmaxf(a.x, b.x); a.y = fmaxf(a.y, b.y);
        a.z = fmaxf(a.z, b.z); a.w = fmaxf(a.w, b.w);
    };
    auto gload = [&](int t) {
        const int k0 = t << 4;
        ra = rb0 = rb1 = make_float4(-NEG, -NEG, -NEG, -NEG);
        if (a_valid && (PATCH || (k0 + a_k < kLen))) {
            if (PATCH) {
                ra = *reinterpret_cast<const float4*>(a_src + t * 224);
            } else {
                ra = *reinterpret_cast<const float4*>(a_src + k0);
#pragma unroll
                for (int c = 1; c < ACMB; c++)
                    fmax4(ra, *reinterpret_cast<const float4*>(a_src + c * aPart + k0));
            }
        }
        if (BMODE == 0) {
            if (b_valid0) {
                if (k0 + b_k8 < kLen) {
                    rb0 = *reinterpret_cast<const float4*>(b_src0 + k0);
#pragma unroll
                    for (int c = 1; c < BCMB; c++)
                        fmax4(rb0, *reinterpret_cast<const float4*>(b_src0 + c * bPart + k0));
                }
                if (k0 + b_k8 + 4 < kLen) {
                    rb1 = *reinterpret_cast<const float4*>(b_src0 + k0 + 4);
#pragma unroll
                    for (int c = 1; c < BCMB; c++)
                        fmax4(rb1, *reinterpret_cast<const float4*>(b_src0 + c * bPart + k0 + 4));
                }
            }
        } else {
            if (k0 + b_k1 < kLen) {
                const float* p = b_src1 + (long)k0 * Nc;
                rb0 = *reinterpret_cast<const float4*>(p);
                rb1 = *reinterpret_cast<const float4*>(p + 4);
#pragma unroll
                for (int c = 1; c < BCMB; c++) {
                    fmax4(rb0, *reinterpret_cast<const float4*>(p + c * bPart));
                    fmax4(rb1, *reinterpret_cast<const float4*>(p + c * bPart + 4));
                }
            }
        }
    };
    auto sts = [&](int buf) {
        As[buf][a_k + 0][a_row] = ra.x;
        As[buf][a_k + 1][a_row] = ra.y;
        As[buf][a_k + 2][a_row] = ra.z;
        As[buf][a_k + 3][a_row] = ra.w;
        if (BMODE == 0) {
            Bs[buf][b_k8 + 0][b_n] = rb0.x;
            Bs[buf][b_k8 + 1][b_n] = rb0.y;
            Bs[buf][b_k8 + 2][b_n] = rb0.z;
            Bs[buf][b_k8 + 3][b_n] = rb0.w;
            Bs[buf][b_k8 + 4][b_n] = rb1.x;
            Bs[buf][b_k8 + 5][b_n] = rb1.y;
            Bs[buf][b_k8 + 6][b_n] = rb1.z;
            Bs[buf][b_k8 + 7][b_n] = rb1.w;
        } else {
            *reinterpret_cast<float4*>(&Bs[buf][b_k1][b_n8])     = rb0;
            *reinterpret_cast<float4*>(&Bs[buf][b_k1][b_n8 + 4]) = rb1;
        }
    };

    gload(0);
    sts(0);
    __syncthreads();

    for (int t = 0; t < ntiles; t++) {
        const int cur = t & 1;
        const bool more = (t + 1 < ntiles);
        if (more) gload(t + 1);

#pragma unroll
        for (int kk = 0; kk < 16; kk++) {
            float4 av = *reinterpret_cast<const float4*>(&As[cur][kk][ty << 2]);
            const unsigned long long* bp =
                reinterpret_cast<const unsigned long long*>(&Bs[cur][kk][tx << 2]);
            unsigned long long b01 = bp[0];
            unsigned long long b23 = bp[1];
            unsigned long long a0 = pack2(av.x);
            unsigned long long a1 = pack2(av.y);
            unsigned long long a2p = pack2(av.z);
            unsigned long long a3 = pack2(av.w);
            addmax2(acc[0][0], acc[0][1], a0,  b01);
            addmax2(acc[0][2], acc[0][3], a0,  b23);
            addmax2(acc[1][0], acc[1][1], a1,  b01);
            addmax2(acc[1][2], acc[1][3], a1,  b23);
            addmax2(acc[2][0], acc[2][1], a2p, b01);
            addmax2(acc[2][2], acc[2][3], a2p, b23);
            addmax2(acc[3][0], acc[3][1], a3,  b01);
            addmax2(acc[3][2], acc[3][3], a3,  b23);
        }
        if (more) { sts((t + 1) & 1); __syncthreads(); }
    }

    const float tauv = (epi == 2) ? epi_ptr[0] : 0.f;
#pragma unroll
    for (int i = 0; i < 4; i++) {
        int gm = bm + (ty << 2) + i;
        if (gm >= Mr) continue;
        int gn = bn + (tx << 2);
        if (gn >= Nc) continue;
        float4 v = make_float4(acc[i][0], acc[i][1], acc[i][2], acc[i][3]);
        if (epi == 1) {
            float4 p = *reinterpret_cast<const float4*>(&epi_ptr[(long)(gm % 196) * Nc + gn]);
            v.x += p.x; v.y += p.y; v.z += p.z; v.w += p.w;
        } else if (epi == 2) {
            v.x = fmaxf(v.x, tauv); v.y = fmaxf(v.y, tauv);
            v.z = fmaxf(v.z, tauv); v.w = fmaxf(v.w, tauv);
        }
        *reinterpret_cast<float4*>(Cm + (long)gm * Nc + gn) = v;
    }
}

// ------ embed combine: h = max of 4 partials; xn = pnorm(h) -----------------
__global__ void embed_combine4(const float* __restrict__ A, long stride,
                               float* __restrict__ H, float* __restrict__ XN, int rows) {
    int row = blockIdx.x * 8 + (threadIdx.x >> 5);
    if (row >= rows) return;
    int lane = threadIdx.x & 31;
    long off = (long)row * D;
    float4 a = reinterpret_cast<const float4*>(A + off)[lane];
#pragma unroll
    for (int c = 1; c < 4; c++) {
        float4 b = reinterpret_cast<const float4*>(A + c * stride + off)[lane];
        a.x = fmaxf(a.x, b.x); a.y = fmaxf(a.y, b.y);
        a.z = fmaxf(a.z, b.z); a.w = fmaxf(a.w, b.w);
    }
    reinterpret_cast<float4*>(H + off)[lane] = a;
    float m = fmaxf(fmaxf(a.x, a.y), fmaxf(a.z, a.w));
#pragma unroll
    for (int o = 16; o; o >>= 1) m = fmaxf(m, __shfl_xor_sync(0xffffffffu, m, o));
    float4 r = make_float4(a.x - m, a.y - m, a.z - m, a.w - m);
    reinterpret_cast<float4*>(XN + off)[lane] = r;
}

// --- residual4: a = max of 4 partials; h = max(h, pnorm(a)); opt xn=pnorm(h) -
__global__ void residual4(const float* __restrict__ A, long stride,
                          float* __restrict__ H, float* __restrict__ XN, int rows) {
    int row = blockIdx.x * 8 + (threadIdx.x >> 5);
    if (row >= rows) return;
    int lane = threadIdx.x & 31;
    long off = (long)row * D;
    float4 a = reinterpret_cast<const float4*>(A + off)[lane];
#pragma unroll
    for (int c = 1; c < 4; c++) {
        float4 b = reinterpret_cast<const float4*>(A + c * stride + off)[lane];
        a.x = fmaxf(a.x, b.x); a.y = fmaxf(a.y, b.y);
        a.z = fmaxf(a.z, b.z); a.w = fmaxf(a.w, b.w);
    }
    float m = fmaxf(fmaxf(a.x, a.y), fmaxf(a.z, a.w));
#pragma unroll
    for (int o = 16; o; o >>= 1) m = fmaxf(m, __shfl_xor_sync(0xffffffffu, m, o));
    float4 h = reinterpret_cast<const float4*>(H + off)[lane];
    h.x = fmaxf(h.x, a.x - m); h.y = fmaxf(h.y, a.y - m);
    h.z = fmaxf(h.z, a.z - m); h.w = fmaxf(h.w, a.w - m);
    reinterpret_cast<float4*>(H + off)[lane] = h;
    if (XN) {
        float m2 = fmaxf(fmaxf(h.x, h.y), fmaxf(h.z, h.w));
#pragma unroll
        for (int o = 16; o; o >>= 1) m2 = fmaxf(m2, __shfl_xor_sync(0xffffffffu, m2, o));
        float4 r = make_float4(h.x - m2, h.y - m2, h.z - m2, h.w - m2);
        reinterpret_cast<float4*>(XN + off)[lane] = r;
    }
}

// ---------------- global tropical pool over patches -------------------------
__global__ void pool_kernel(const float* __restrict__ H, float* __restrict__ Pl) {
    int b = blockIdx.x, d = threadIdx.x;
    float m = -NEG;
    const float* p = H + (long)b * Npat * D + d;
    for (int n = 0; n < Npat; n++) m = fmaxf(m, p[n * D]);
    Pl[b * D + d] = m;
}

// ---------------- head ------------------------------------------------------
__global__ void head_kernel(const float* __restrict__ Pl, const float* __restrict__ W,
                            const float* __restrict__ ls, float* __restrict__ out) {
    int w = blockIdx.x * 8 + (threadIdx.x >> 5);
    int lane = threadIdx.x & 31;
    int b = w / Cls, c = w % Cls;
    if (b >= Bsz) return;
    const float* p = Pl + b * D;
    const float* wr = W + (long)c * D;
    float m = -NEG;
#pragma unroll
    for (int k = 0; k < 4; k++) {
        int idx = lane + 32 * k;
        m = fmaxf(m, p[idx] + wr[idx]);
    }
#pragma unroll
    for (int o = 16; o; o >>= 1) m = fmaxf(m, __shfl_xor_sync(0xffffffffu, m, o));
    if (lane == 0) out[b * Cls + c] = m * ls[0];
}

// ---------------------------------------------------------------------------
extern "C" void kernel_launch(void* const* d_in, const int* in_sizes, int n_in,
                              void* d_out, int out_size) {
    const float* x       = (const float*)d_in[0];
    const float* embed_W = (const float*)d_in[1];
    const float* pos     = (const float*)d_in[2];
    const float* qW[2]  = {(const float*)d_in[3],  (const float*)d_in[9]};
    const float* kW[2]  = {(const float*)d_in[4],  (const float*)d_in[10]};
    const float* vW[2]  = {(const float*)d_in[5],  (const float*)d_in[11]};
    const float* f1W[2] = {(const float*)d_in[6],  (const float*)d_in[12]};
    const float* f2W[2] = {(const float*)d_in[7],  (const float*)d_in[13]};
    const float* tau[2] = {(const float*)d_in[8],  (const float*)d_in[14]};
    const float* headW  = (const float*)d_in[15];
    const float* ls     = (const float*)d_in[16];
    float* out = (float*)d_out;

    void *h, *xn, *qkv, *sc, *attn, *ffh, *ffo, *pool;
    cudaGetSymbolAddress(&h,    g_h);
    cudaGetSymbolAddress(&xn,   g_xn);
    cudaGetSymbolAddress(&qkv,  g_qkv);
    cudaGetSymbolAddress(&sc,   g_sc);
    cudaGetSymbolAddress(&attn, g_attn);
    cudaGetSymbolAddress(&ffh,  g_ffh);
    cudaGetSymbolAddress(&ffo,  g_ffo);
    cudaGetSymbolAddress(&pool, g_pool);

    float* fh    = (float*)h;
    float* fxn   = (float*)xn;
    float* fq    = (float*)qkv;          // q partials [0,1]·MD
    float* fk    = fq + 2 * MD;          // k partials [2,3]·MD
    float* fv    = fq + 4 * MD;          // v partials [4,5]·MD
    float* fsc   = (float*)sc;
    float* fattn = (float*)attn;
    float* fffh  = (float*)ffh;
    float* fffo  = (float*)ffo;
    float* fpool = (float*)pool;

    // embed (patchify fused, K=256 split 4) -> 4 partials in g_attn
    trop_gemm<0, 1, 4, 1, 1><<<dim3(49, 2, 4), 128>>>(
        x, embed_W, nullptr, nullptr, fattn,
        Mrows, D, 256, 0, 0, 0, MD, 0, 0, 64, 1, pos);
    embed_combine4<<<196, 256>>>(fattn, MD, fh, fxn, Mrows);

    for (int l = 0; l < 2; l++) {
        // fused q/k/v, K=128 split 2 -> 2 partials each
        trop_gemm<0, 0, 2, 1, 1><<<dim3(49, 2, 6), 128>>>(
            fxn, qW[l], kW[l], vW[l], fq,
            Mrows, D, D, 0, 0, 2 * MD, MD, 0, 0, 64, 0, nullptr);

        // scores, combine q/k partials at staging; K=128 split 4
        trop_gemm<0, 0, 4, 2, 2><<<dim3(7, 4, 32), 128>>>(
            fq, fk, nullptr, nullptr, fsc,
            Npat, Npat, D, NpD, NpD, NpN, (long)Bsz * NpN, MD, MD, 32, 0, nullptr);

        // attn-out: A = max of 4 score partials, B = max of 2 v partials; K=196 split 4
        trop_gemm<1, 0, 4, 4, 2><<<dim3(7, 2, 32), 128>>>(
            fsc, fv, nullptr, nullptr, fattn,
            Npat, D, Npat, NpN, NpD, NpD, MD, (long)Bsz * NpN, MD, 52, 0, nullptr);

        residual4<<<196, 256>>>(fattn, MD, fh, fxn, Mrows);

        // ff1, K=128 split 4 -> 4 partials (tau epilogue distributes over max)
        trop_gemm<0, 0, 4, 1, 1><<<dim3(49, 4, 4), 128>>>(
            fxn, f1W[l], nullptr, nullptr, fffh,
            Mrows, DFF, D, 0, 0, 0, MDFF, 0, 0, 32, 2, tau[l]);

        // ff2: A = max of 4 ffh partials; K=256 split 4
        trop_gemm<0, 0, 4, 4, 1><<<dim3(49, 2, 4), 128>>>(
            fffh, f2W[l], nullptr, nullptr, fffo,
            Mrows, D, DFF, 0, 0, 0, MD, MDFF, 0, 64, 0, nullptr);

        residual4<<<196, 256>>>(fffo, MD, fh, (l == 0) ? fxn : nullptr, Mrows);
    }

    pool_kernel<<<Bsz, D>>>(fh, fpool);
    head_kernel<<<1000, 256>>>(fpool, headW, ls, out);
}